// round 1
// baseline (speedup 1.0000x reference)
#include <cuda_runtime.h>
#include <cuda_bf16.h>
#include <math.h>

#define B_   2
#define S_   2048
#define NH_  16
#define NKV_ 8
#define HD_  128
#define MROWS (B_ * S_)          // 4096

// ---------------- scratch (device globals; no allocation allowed) ----------
__device__ float g_q[(size_t)B_ * S_ * NH_ * HD_];     // 8M floats
__device__ float g_k[(size_t)B_ * S_ * NKV_ * HD_];    // 4M floats
__device__ float g_v[(size_t)B_ * S_ * NKV_ * HD_];    // 4M floats
__device__ float g_attn[(size_t)B_ * S_ * NH_ * HD_];  // 8M floats
__device__ float g_cos[S_ * 64];
__device__ float g_sin[S_ * 64];

// ============================================================================
// SGEMM: C[M,N] = A[M,K] @ B[K,N], all row-major, fp32.
// 128x128 tile, BK=16, 256 threads, 8x8 micro-tile.
// ============================================================================
#define GTM 128
#define GTN 128
#define GTK 16

__global__ __launch_bounds__(256, 2)
void sgemm_kernel(const float* __restrict__ A, const float* __restrict__ B,
                  float* __restrict__ C, int M, int N, int K) {
    __shared__ float As[GTK][132];   // transposed: As[k][m], padded
    __shared__ float Bs[GTK][GTN];

    const int tid = threadIdx.x;
    const int ty = tid >> 4;         // 0..15
    const int tx = tid & 15;         // 0..15
    const int m0 = blockIdx.y * GTM;
    const int n0 = blockIdx.x * GTN;

    float acc[8][8];
#pragma unroll
    for (int i = 0; i < 8; i++)
#pragma unroll
        for (int j = 0; j < 8; j++) acc[i][j] = 0.0f;

    const int a_m = tid >> 2;          // 0..63
    const int a_k = (tid & 3) << 2;    // 0,4,8,12
    const int b_k = tid >> 5;          // 0..7
    const int b_n = (tid & 31) << 2;   // 0..124

    for (int k0 = 0; k0 < K; k0 += GTK) {
#pragma unroll
        for (int it = 0; it < 2; it++) {
            int m = a_m + it * 64;
            float4 av = *(const float4*)&A[(size_t)(m0 + m) * K + k0 + a_k];
            As[a_k + 0][m] = av.x;
            As[a_k + 1][m] = av.y;
            As[a_k + 2][m] = av.z;
            As[a_k + 3][m] = av.w;
        }
#pragma unroll
        for (int it = 0; it < 2; it++) {
            int kk = b_k + it * 8;
            *(float4*)&Bs[kk][b_n] =
                *(const float4*)&B[(size_t)(k0 + kk) * N + n0 + b_n];
        }
        __syncthreads();

#pragma unroll
        for (int kk = 0; kk < GTK; kk++) {
            float a[8], bb[8];
            *(float4*)&a[0]  = *(const float4*)&As[kk][ty * 8];
            *(float4*)&a[4]  = *(const float4*)&As[kk][ty * 8 + 4];
            *(float4*)&bb[0] = *(const float4*)&Bs[kk][tx * 8];
            *(float4*)&bb[4] = *(const float4*)&Bs[kk][tx * 8 + 4];
#pragma unroll
            for (int i = 0; i < 8; i++)
#pragma unroll
                for (int j = 0; j < 8; j++)
                    acc[i][j] += a[i] * bb[j];
        }
        __syncthreads();
    }

#pragma unroll
    for (int i = 0; i < 8; i++) {
        float* cp = &C[(size_t)(m0 + ty * 8 + i) * N + n0 + tx * 8];
        *(float4*)cp       = make_float4(acc[i][0], acc[i][1], acc[i][2], acc[i][3]);
        *(float4*)(cp + 4) = make_float4(acc[i][4], acc[i][5], acc[i][6], acc[i][7]);
    }
}

// ============================================================================
// RoPE cos/sin table: [S, 64]
// ============================================================================
__global__ void rope_table_kernel(const int* __restrict__ pos,
                                  float* __restrict__ ctab,
                                  float* __restrict__ stab) {
    int idx = blockIdx.x * blockDim.x + threadIdx.x;
    if (idx >= S_ * 64) return;
    int s  = idx >> 6;
    int fi = idx & 63;
    // inv_freq = base^(-fi/64), computed in double for cleanliness
    float inv = (float)exp(-13.815510557964274 * (double)fi / 64.0);
    float ang = (float)pos[s] * inv;
    float c, sn;
    sincosf(ang, &sn, &c);
    ctab[idx] = c;
    stab[idx] = sn;
}

// ============================================================================
// RMSNorm + RoPE in-place over g_q (65536 rows) and g_k (32768 rows).
// One warp per 128-wide head row.
// ============================================================================
__global__ void norm_rope_kernel(float* __restrict__ q, float* __restrict__ k,
                                 const float* __restrict__ qw,
                                 const float* __restrict__ kw,
                                 const float* __restrict__ ctab,
                                 const float* __restrict__ stab) {
    const int warp = (blockIdx.x * blockDim.x + threadIdx.x) >> 5;
    const int lane = threadIdx.x & 31;
    const int QROWS = B_ * S_ * NH_;   // 65536

    float* ptr;
    const float* w;
    int s;
    if (warp < QROWS) {
        ptr = q + (size_t)warp * HD_;
        w = qw;
        s = (warp / NH_) % S_;
    } else {
        int r = warp - QROWS;
        ptr = k + (size_t)r * HD_;
        w = kw;
        s = (r / NKV_) % S_;
    }

    float4 x = ((const float4*)ptr)[lane];
    float ss = x.x * x.x + x.y * x.y + x.z * x.z + x.w * x.w;
#pragma unroll
    for (int off = 16; off; off >>= 1)
        ss += __shfl_xor_sync(0xffffffffu, ss, off);
    float rms = rsqrtf(ss * (1.0f / 128.0f) + 1e-6f);

    const int d0 = lane * 4;
    float xn[4];
    xn[0] = x.x * rms * w[d0 + 0];
    xn[1] = x.y * rms * w[d0 + 1];
    xn[2] = x.z * rms * w[d0 + 2];
    xn[3] = x.w * rms * w[d0 + 3];

    float out[4];
#pragma unroll
    for (int j = 0; j < 4; j++) {
        int fi = (d0 + j) & 63;
        float c  = ctab[s * 64 + fi];
        float sn = stab[s * 64 + fi];
        float partner = __shfl_xor_sync(0xffffffffu, xn[j], 16);
        out[j] = (lane < 16) ? (xn[j] * c - partner * sn)
                             : (xn[j] * c + partner * sn);
    }
    ((float4*)ptr)[lane] = make_float4(out[0], out[1], out[2], out[3]);
}

// ============================================================================
// Flash attention, fp32, causal, GQA (2 q-heads per kv head).
// BM=BN=64, HD=128, 128 threads. Thread grid 8x16:
//   scores: rows trow*8+i (8), cols tcol*4+j (4)
//   O:      rows trow*8+i (8), cols tcol*8+jj (8)
// ============================================================================
__global__ __launch_bounds__(128, 2)
void attn_kernel(const float* __restrict__ q, const float* __restrict__ k,
                 const float* __restrict__ v, float* __restrict__ o) {
    extern __shared__ float sm[];
    float* Qs  = sm;               // [64][132]
    float* KVs = sm + 64 * 132;    // [64][132] (K then V)
    float* Ps  = sm + 2 * 64 * 132;// [64][64]

    const int tid = threadIdx.x;
    const int bh = blockIdx.y;
    const int b  = bh >> 4;
    const int h  = bh & 15;
    const int hk = h >> 1;
    const int qtile = gridDim.x - 1 - blockIdx.x;  // heavy tiles first
    const int q0 = qtile * 64;
    const float scale = 0.08838834764831845f;      // 1/sqrt(128)

    // load Q tile (pre-scaled)
#pragma unroll
    for (int t = 0; t < 16; t++) {
        int idx = t * 128 + tid;
        int r  = idx >> 5;
        int d4 = (idx & 31) << 2;
        float4 qv = *(const float4*)
            &q[((size_t)(b * S_ + q0 + r) * NH_ + h) * HD_ + d4];
        *(float4*)&Qs[r * 132 + d4] =
            make_float4(qv.x * scale, qv.y * scale, qv.z * scale, qv.w * scale);
    }

    const int trow = tid >> 4;   // 0..7
    const int tcol = tid & 15;   // 0..15

    float m_i[8], l_i[8], acc[8][8];
#pragma unroll
    for (int i = 0; i < 8; i++) {
        m_i[i] = -1e30f;
        l_i[i] = 0.0f;
#pragma unroll
        for (int j = 0; j < 8; j++) acc[i][j] = 0.0f;
    }

    for (int kt = 0; kt <= qtile; kt++) {
        const int k0 = kt * 64;
        __syncthreads();   // protect KVs from previous iteration's PV reads

        // load K tile
#pragma unroll
        for (int t = 0; t < 16; t++) {
            int idx = t * 128 + tid;
            int r  = idx >> 5;
            int d4 = (idx & 31) << 2;
            *(float4*)&KVs[r * 132 + d4] = *(const float4*)
                &k[((size_t)(b * S_ + k0 + r) * NKV_ + hk) * HD_ + d4];
        }
        __syncthreads();

        // scores
        float sc[8][4];
#pragma unroll
        for (int i = 0; i < 8; i++)
#pragma unroll
            for (int j = 0; j < 4; j++) sc[i][j] = 0.0f;

        for (int d4 = 0; d4 < 128; d4 += 4) {
            float4 kv[4];
#pragma unroll
            for (int j = 0; j < 4; j++)
                kv[j] = *(const float4*)&KVs[(tcol * 4 + j) * 132 + d4];
#pragma unroll
            for (int i = 0; i < 8; i++) {
                float4 qv = *(const float4*)&Qs[(trow * 8 + i) * 132 + d4];
#pragma unroll
                for (int j = 0; j < 4; j++)
                    sc[i][j] += qv.x * kv[j].x + qv.y * kv[j].y +
                                qv.z * kv[j].z + qv.w * kv[j].w;
            }
        }

        // causal mask on the diagonal tile (q0 == k0 there)
        if (kt == qtile) {
#pragma unroll
            for (int i = 0; i < 8; i++)
#pragma unroll
                for (int j = 0; j < 4; j++)
                    if (tcol * 4 + j > trow * 8 + i) sc[i][j] = -1e30f;
        }

        // online softmax update
        float p_[8][4];
#pragma unroll
        for (int i = 0; i < 8; i++) {
            float mx = fmaxf(fmaxf(sc[i][0], sc[i][1]), fmaxf(sc[i][2], sc[i][3]));
#pragma unroll
            for (int off = 8; off; off >>= 1)
                mx = fmaxf(mx, __shfl_xor_sync(0xffffffffu, mx, off));
            float mn = fmaxf(m_i[i], mx);
            float alpha = __expf(m_i[i] - mn);
            float rs = 0.0f;
#pragma unroll
            for (int j = 0; j < 4; j++) {
                p_[i][j] = __expf(sc[i][j] - mn);
                rs += p_[i][j];
            }
#pragma unroll
            for (int off = 8; off; off >>= 1)
                rs += __shfl_xor_sync(0xffffffffu, rs, off);
            l_i[i] = l_i[i] * alpha + rs;
            m_i[i] = mn;
#pragma unroll
            for (int jj = 0; jj < 8; jj++) acc[i][jj] *= alpha;
        }

        __syncthreads();  // everyone done reading K; prev Ps fully consumed

        // stage P, load V into the K buffer
#pragma unroll
        for (int i = 0; i < 8; i++)
            *(float4*)&Ps[(trow * 8 + i) * 64 + tcol * 4] =
                make_float4(p_[i][0], p_[i][1], p_[i][2], p_[i][3]);
#pragma unroll
        for (int t = 0; t < 16; t++) {
            int idx = t * 128 + tid;
            int r  = idx >> 5;
            int d4 = (idx & 31) << 2;
            *(float4*)&KVs[r * 132 + d4] = *(const float4*)
                &v[((size_t)(b * S_ + k0 + r) * NKV_ + hk) * HD_ + d4];
        }
        __syncthreads();

        // O += P @ V
        for (int n4 = 0; n4 < 64; n4 += 4) {
            float pr[8][4];
#pragma unroll
            for (int i = 0; i < 8; i++) {
                float4 t4 = *(const float4*)&Ps[(trow * 8 + i) * 64 + n4];
                pr[i][0] = t4.x; pr[i][1] = t4.y; pr[i][2] = t4.z; pr[i][3] = t4.w;
            }
#pragma unroll
            for (int u = 0; u < 4; u++) {
                float4 v0 = *(const float4*)&KVs[(n4 + u) * 132 + tcol * 8];
                float4 v1 = *(const float4*)&KVs[(n4 + u) * 132 + tcol * 8 + 4];
#pragma unroll
                for (int i = 0; i < 8; i++) {
                    float pw = pr[i][u];
                    acc[i][0] += pw * v0.x;
                    acc[i][1] += pw * v0.y;
                    acc[i][2] += pw * v0.z;
                    acc[i][3] += pw * v0.w;
                    acc[i][4] += pw * v1.x;
                    acc[i][5] += pw * v1.y;
                    acc[i][6] += pw * v1.z;
                    acc[i][7] += pw * v1.w;
                }
            }
        }
    }

    // epilogue: O /= l, write out in [b][s][h][d] layout
#pragma unroll
    for (int i = 0; i < 8; i++) {
        float inv = 1.0f / l_i[i];
        float* op = &o[((size_t)(b * S_ + q0 + trow * 8 + i) * NH_ + h) * HD_ +
                       tcol * 8];
        *(float4*)op = make_float4(acc[i][0] * inv, acc[i][1] * inv,
                                   acc[i][2] * inv, acc[i][3] * inv);
        *(float4*)(op + 4) = make_float4(acc[i][4] * inv, acc[i][5] * inv,
                                         acc[i][6] * inv, acc[i][7] * inv);
    }
}

// ============================================================================
// launch
// ============================================================================
extern "C" void kernel_launch(void* const* d_in, const int* in_sizes, int n_in,
                              void* d_out, int out_size) {
    const float* hidden = (const float*)d_in[0];
    const int*   pos    = (const int*)d_in[1];
    const float* Wq     = (const float*)d_in[2];
    const float* Wk     = (const float*)d_in[3];
    const float* Wv     = (const float*)d_in[4];
    const float* Wo     = (const float*)d_in[5];
    const float* qw     = (const float*)d_in[6];
    const float* kw     = (const float*)d_in[7];
    float* out = (float*)d_out;

    float *q, *k, *v, *attn, *ct, *st;
    cudaGetSymbolAddress((void**)&q,    g_q);
    cudaGetSymbolAddress((void**)&k,    g_k);
    cudaGetSymbolAddress((void**)&v,    g_v);
    cudaGetSymbolAddress((void**)&attn, g_attn);
    cudaGetSymbolAddress((void**)&ct,   g_cos);
    cudaGetSymbolAddress((void**)&st,   g_sin);

    // QKV projections
    sgemm_kernel<<<dim3((NH_ * HD_) / GTN, MROWS / GTM), 256>>>(
        hidden, Wq, q, MROWS, NH_ * HD_, 1024);
    sgemm_kernel<<<dim3((NKV_ * HD_) / GTN, MROWS / GTM), 256>>>(
        hidden, Wk, k, MROWS, NKV_ * HD_, 1024);
    sgemm_kernel<<<dim3((NKV_ * HD_) / GTN, MROWS / GTM), 256>>>(
        hidden, Wv, v, MROWS, NKV_ * HD_, 1024);

    // RoPE table + RMSNorm/RoPE
    rope_table_kernel<<<(S_ * 64 + 255) / 256, 256>>>(pos, ct, st);
    {
        int total_warps = B_ * S_ * (NH_ + NKV_);   // 98304
        norm_rope_kernel<<<total_warps / 8, 256>>>(q, k, qw, kw, ct, st);
    }

    // attention
    {
        size_t smem = (size_t)(2 * 64 * 132 + 64 * 64) * sizeof(float); // 83968 B
        cudaFuncSetAttribute(attn_kernel,
                             cudaFuncAttributeMaxDynamicSharedMemorySize,
                             (int)smem);
        attn_kernel<<<dim3(S_ / 64, B_ * NH_), 128, smem>>>(q, k, v, attn);
    }

    // output projection
    sgemm_kernel<<<dim3(1024 / GTN, MROWS / GTM), 256>>>(
        attn, Wo, out, MROWS, 1024, NH_ * HD_);
}

// round 2
// speedup vs baseline: 1.0407x; 1.0407x over previous
#include <cuda_runtime.h>
#include <cuda_bf16.h>
#include <math.h>

#define B_   2
#define S_   2048
#define NH_  16
#define NKV_ 8
#define HD_  128
#define MROWS (B_ * S_)          // 4096

// ---------------- scratch (device globals; no allocation allowed) ----------
__device__ float g_q[(size_t)B_ * S_ * NH_ * HD_];     // 8M floats
__device__ float g_k[(size_t)B_ * S_ * NKV_ * HD_];    // 4M floats
__device__ float g_v[(size_t)B_ * S_ * NKV_ * HD_];    // 4M floats
__device__ float g_attn[(size_t)B_ * S_ * NH_ * HD_];  // 8M floats
__device__ float g_cos[S_ * 64];
__device__ float g_sin[S_ * 64];

// ---------------- packed f32x2 helpers (sm_103a FFMA2 path) ----------------
typedef unsigned long long u64;

__device__ __forceinline__ void ffma2(u64& d, u64 a, u64 b) {
    asm("fma.rn.f32x2 %0, %1, %2, %0;" : "+l"(d) : "l"(a), "l"(b));
}
__device__ __forceinline__ void fmul2(u64& d, u64 a, u64 b) {
    asm("mul.rn.f32x2 %0, %1, %2;" : "=l"(d) : "l"(a), "l"(b));
}
__device__ __forceinline__ u64 pack_dup(float x) {
    u64 r;
    asm("mov.b64 %0, {%1, %1};" : "=l"(r) : "f"(x));
    return r;
}
__device__ __forceinline__ float2 unpack2(u64 p) {
    float lo, hi;
    asm("mov.b64 {%0, %1}, %2;" : "=f"(lo), "=f"(hi) : "l"(p));
    return make_float2(lo, hi);
}

// ============================================================================
// SGEMM: C[M,N] = A[M,K] @ B[K,N], all row-major, fp32, FFMA2 inner loop.
// 128x128 tile, BK=16, 256 threads, 8x8 micro-tile (acc packed along j).
// ============================================================================
#define GTM 128
#define GTN 128
#define GTK 16

__global__ __launch_bounds__(256, 2)
void sgemm_kernel(const float* __restrict__ A, const float* __restrict__ B,
                  float* __restrict__ C, int M, int N, int K) {
    __shared__ float As[GTK][132];   // transposed: As[k][m], padded
    __shared__ float Bs[GTK][GTN];

    const int tid = threadIdx.x;
    const int ty = tid >> 4;         // 0..15
    const int tx = tid & 15;         // 0..15
    const int m0 = blockIdx.y * GTM;
    const int n0 = blockIdx.x * GTN;

    u64 acc2[8][4];
#pragma unroll
    for (int i = 0; i < 8; i++)
#pragma unroll
        for (int j = 0; j < 4; j++) acc2[i][j] = 0ULL;

    const int a_m = tid >> 2;          // 0..63
    const int a_k = (tid & 3) << 2;    // 0,4,8,12
    const int b_k = tid >> 5;          // 0..7
    const int b_n = (tid & 31) << 2;   // 0..124

    for (int k0 = 0; k0 < K; k0 += GTK) {
#pragma unroll
        for (int it = 0; it < 2; it++) {
            int m = a_m + it * 64;
            float4 av = *(const float4*)&A[(size_t)(m0 + m) * K + k0 + a_k];
            As[a_k + 0][m] = av.x;
            As[a_k + 1][m] = av.y;
            As[a_k + 2][m] = av.z;
            As[a_k + 3][m] = av.w;
        }
#pragma unroll
        for (int it = 0; it < 2; it++) {
            int kk = b_k + it * 8;
            *(float4*)&Bs[kk][b_n] =
                *(const float4*)&B[(size_t)(k0 + kk) * N + n0 + b_n];
        }
        __syncthreads();

#pragma unroll
        for (int kk = 0; kk < GTK; kk++) {
            float a[8];
            *(float4*)&a[0] = *(const float4*)&As[kk][ty * 8];
            *(float4*)&a[4] = *(const float4*)&As[kk][ty * 8 + 4];
            ulonglong2 b01 = *(const ulonglong2*)&Bs[kk][tx * 8];
            ulonglong2 b23 = *(const ulonglong2*)&Bs[kk][tx * 8 + 4];
#pragma unroll
            for (int i = 0; i < 8; i++) {
                u64 a2 = pack_dup(a[i]);
                ffma2(acc2[i][0], a2, b01.x);
                ffma2(acc2[i][1], a2, b01.y);
                ffma2(acc2[i][2], a2, b23.x);
                ffma2(acc2[i][3], a2, b23.y);
            }
        }
        __syncthreads();
    }

#pragma unroll
    for (int i = 0; i < 8; i++) {
        u64* cp = (u64*)&C[(size_t)(m0 + ty * 8 + i) * N + n0 + tx * 8];
        cp[0] = acc2[i][0];
        cp[1] = acc2[i][1];
        cp[2] = acc2[i][2];
        cp[3] = acc2[i][3];
    }
}

// ============================================================================
// RoPE cos/sin table: [S, 64]
// ============================================================================
__global__ void rope_table_kernel(const int* __restrict__ pos,
                                  float* __restrict__ ctab,
                                  float* __restrict__ stab) {
    int idx = blockIdx.x * blockDim.x + threadIdx.x;
    if (idx >= S_ * 64) return;
    int s  = idx >> 6;
    int fi = idx & 63;
    float inv = (float)exp(-13.815510557964274 * (double)fi / 64.0);
    float ang = (float)pos[s] * inv;
    float c, sn;
    sincosf(ang, &sn, &c);
    ctab[idx] = c;
    stab[idx] = sn;
}

// ============================================================================
// RMSNorm + RoPE in-place over g_q (65536 rows) and g_k (32768 rows).
// ============================================================================
__global__ void norm_rope_kernel(float* __restrict__ q, float* __restrict__ k,
                                 const float* __restrict__ qw,
                                 const float* __restrict__ kw,
                                 const float* __restrict__ ctab,
                                 const float* __restrict__ stab) {
    const int warp = (blockIdx.x * blockDim.x + threadIdx.x) >> 5;
    const int lane = threadIdx.x & 31;
    const int QROWS = B_ * S_ * NH_;   // 65536

    float* ptr;
    const float* w;
    int s;
    if (warp < QROWS) {
        ptr = q + (size_t)warp * HD_;
        w = qw;
        s = (warp / NH_) % S_;
    } else {
        int r = warp - QROWS;
        ptr = k + (size_t)r * HD_;
        w = kw;
        s = (r / NKV_) % S_;
    }

    float4 x = ((const float4*)ptr)[lane];
    float ss = x.x * x.x + x.y * x.y + x.z * x.z + x.w * x.w;
#pragma unroll
    for (int off = 16; off; off >>= 1)
        ss += __shfl_xor_sync(0xffffffffu, ss, off);
    float rms = rsqrtf(ss * (1.0f / 128.0f) + 1e-6f);

    const int d0 = lane * 4;
    float xn[4];
    xn[0] = x.x * rms * w[d0 + 0];
    xn[1] = x.y * rms * w[d0 + 1];
    xn[2] = x.z * rms * w[d0 + 2];
    xn[3] = x.w * rms * w[d0 + 3];

    float out[4];
#pragma unroll
    for (int j = 0; j < 4; j++) {
        int fi = (d0 + j) & 63;
        float c  = ctab[s * 64 + fi];
        float sn = stab[s * 64 + fi];
        float partner = __shfl_xor_sync(0xffffffffu, xn[j], 16);
        out[j] = (lane < 16) ? (xn[j] * c - partner * sn)
                             : (xn[j] * c + partner * sn);
    }
    ((float4*)ptr)[lane] = make_float4(out[0], out[1], out[2], out[3]);
}

// ============================================================================
// Flash attention, fp32, causal, GQA. FFMA2 inner loops.
// BM=BN=64, HD=128, 128 threads. Thread grid 8x16.
// ============================================================================
__global__ __launch_bounds__(128, 2)
void attn_kernel(const float* __restrict__ q, const float* __restrict__ k,
                 const float* __restrict__ v, float* __restrict__ o) {
    extern __shared__ float sm[];
    float* Qs  = sm;               // [64][132]
    float* KVs = sm + 64 * 132;    // [64][132] (K then V)
    float* Ps  = sm + 2 * 64 * 132;// [64][64]

    const int tid = threadIdx.x;
    const int bh = blockIdx.y;
    const int b  = bh >> 4;
    const int h  = bh & 15;
    const int hk = h >> 1;
    const int qtile = gridDim.x - 1 - blockIdx.x;  // heavy tiles first
    const int q0 = qtile * 64;
    const float scale = 0.08838834764831845f;      // 1/sqrt(128)

    // load Q tile (pre-scaled)
#pragma unroll
    for (int t = 0; t < 16; t++) {
        int idx = t * 128 + tid;
        int r  = idx >> 5;
        int d4 = (idx & 31) << 2;
        float4 qv = *(const float4*)
            &q[((size_t)(b * S_ + q0 + r) * NH_ + h) * HD_ + d4];
        *(float4*)&Qs[r * 132 + d4] =
            make_float4(qv.x * scale, qv.y * scale, qv.z * scale, qv.w * scale);
    }

    const int trow = tid >> 4;   // 0..7
    const int tcol = tid & 15;   // 0..15

    float m_i[8], l_i[8];
    u64 acc2[8][4];              // O accumulators, packed along output column
#pragma unroll
    for (int i = 0; i < 8; i++) {
        m_i[i] = -1e30f;
        l_i[i] = 0.0f;
#pragma unroll
        for (int j = 0; j < 4; j++) acc2[i][j] = 0ULL;
    }

    for (int kt = 0; kt <= qtile; kt++) {
        const int k0 = kt * 64;
        __syncthreads();   // protect KVs from previous iteration's PV reads

        // load K tile
#pragma unroll
        for (int t = 0; t < 16; t++) {
            int idx = t * 128 + tid;
            int r  = idx >> 5;
            int d4 = (idx & 31) << 2;
            *(float4*)&KVs[r * 132 + d4] = *(const float4*)
                &k[((size_t)(b * S_ + k0 + r) * NKV_ + hk) * HD_ + d4];
        }
        __syncthreads();

        // scores: packed along the d (reduction) dimension — pure 2x
        u64 sc2[8][4];
#pragma unroll
        for (int i = 0; i < 8; i++)
#pragma unroll
            for (int j = 0; j < 4; j++) sc2[i][j] = 0ULL;

        for (int d4 = 0; d4 < 128; d4 += 4) {
            ulonglong2 kv2[4];
#pragma unroll
            for (int j = 0; j < 4; j++)
                kv2[j] = *(const ulonglong2*)&KVs[(tcol * 4 + j) * 132 + d4];
#pragma unroll
            for (int i = 0; i < 8; i++) {
                ulonglong2 qv2 = *(const ulonglong2*)&Qs[(trow * 8 + i) * 132 + d4];
#pragma unroll
                for (int j = 0; j < 4; j++) {
                    ffma2(sc2[i][j], qv2.x, kv2[j].x);
                    ffma2(sc2[i][j], qv2.y, kv2[j].y);
                }
            }
        }

        float sc[8][4];
#pragma unroll
        for (int i = 0; i < 8; i++)
#pragma unroll
            for (int j = 0; j < 4; j++) {
                float2 p = unpack2(sc2[i][j]);
                sc[i][j] = p.x + p.y;
            }

        // causal mask on the diagonal tile
        if (kt == qtile) {
#pragma unroll
            for (int i = 0; i < 8; i++)
#pragma unroll
                for (int j = 0; j < 4; j++)
                    if (tcol * 4 + j > trow * 8 + i) sc[i][j] = -1e30f;
        }

        // online softmax update
        float p_[8][4];
#pragma unroll
        for (int i = 0; i < 8; i++) {
            float mx = fmaxf(fmaxf(sc[i][0], sc[i][1]), fmaxf(sc[i][2], sc[i][3]));
#pragma unroll
            for (int off = 8; off; off >>= 1)
                mx = fmaxf(mx, __shfl_xor_sync(0xffffffffu, mx, off));
            float mn = fmaxf(m_i[i], mx);
            float alpha = __expf(m_i[i] - mn);
            float rs = 0.0f;
#pragma unroll
            for (int j = 0; j < 4; j++) {
                p_[i][j] = __expf(sc[i][j] - mn);
                rs += p_[i][j];
            }
#pragma unroll
            for (int off = 8; off; off >>= 1)
                rs += __shfl_xor_sync(0xffffffffu, rs, off);
            l_i[i] = l_i[i] * alpha + rs;
            m_i[i] = mn;
            u64 al2 = pack_dup(alpha);
#pragma unroll
            for (int jj = 0; jj < 4; jj++) fmul2(acc2[i][jj], acc2[i][jj], al2);
        }

        __syncthreads();  // everyone done reading K; prev Ps fully consumed

        // stage P, load V into the K buffer
#pragma unroll
        for (int i = 0; i < 8; i++)
            *(float4*)&Ps[(trow * 8 + i) * 64 + tcol * 4] =
                make_float4(p_[i][0], p_[i][1], p_[i][2], p_[i][3]);
#pragma unroll
        for (int t = 0; t < 16; t++) {
            int idx = t * 128 + tid;
            int r  = idx >> 5;
            int d4 = (idx & 31) << 2;
            *(float4*)&KVs[r * 132 + d4] = *(const float4*)
                &v[((size_t)(b * S_ + k0 + r) * NKV_ + hk) * HD_ + d4];
        }
        __syncthreads();

        // O += P @ V (packed along output columns)
        for (int n4 = 0; n4 < 64; n4 += 4) {
            float pr[8][4];
#pragma unroll
            for (int i = 0; i < 8; i++) {
                float4 t4 = *(const float4*)&Ps[(trow * 8 + i) * 64 + n4];
                pr[i][0] = t4.x; pr[i][1] = t4.y; pr[i][2] = t4.z; pr[i][3] = t4.w;
            }
#pragma unroll
            for (int u = 0; u < 4; u++) {
                ulonglong2 v01 = *(const ulonglong2*)&KVs[(n4 + u) * 132 + tcol * 8];
                ulonglong2 v23 = *(const ulonglong2*)&KVs[(n4 + u) * 132 + tcol * 8 + 4];
#pragma unroll
                for (int i = 0; i < 8; i++) {
                    u64 pw2 = pack_dup(pr[i][u]);
                    ffma2(acc2[i][0], pw2, v01.x);
                    ffma2(acc2[i][1], pw2, v01.y);
                    ffma2(acc2[i][2], pw2, v23.x);
                    ffma2(acc2[i][3], pw2, v23.y);
                }
            }
        }
    }

    // epilogue: O /= l, write out in [b][s][h][d] layout
#pragma unroll
    for (int i = 0; i < 8; i++) {
        u64 inv2 = pack_dup(1.0f / l_i[i]);
        float* op = &o[((size_t)(b * S_ + q0 + trow * 8 + i) * NH_ + h) * HD_ +
                       tcol * 8];
#pragma unroll
        for (int j = 0; j < 4; j++) {
            u64 r;
            fmul2(r, acc2[i][j], inv2);
            ((u64*)op)[j] = r;
        }
    }
}

// ============================================================================
// launch
// ============================================================================
extern "C" void kernel_launch(void* const* d_in, const int* in_sizes, int n_in,
                              void* d_out, int out_size) {
    const float* hidden = (const float*)d_in[0];
    const int*   pos    = (const int*)d_in[1];
    const float* Wq     = (const float*)d_in[2];
    const float* Wk     = (const float*)d_in[3];
    const float* Wv     = (const float*)d_in[4];
    const float* Wo     = (const float*)d_in[5];
    const float* qw     = (const float*)d_in[6];
    const float* kw     = (const float*)d_in[7];
    float* out = (float*)d_out;

    float *q, *k, *v, *attn, *ct, *st;
    cudaGetSymbolAddress((void**)&q,    g_q);
    cudaGetSymbolAddress((void**)&k,    g_k);
    cudaGetSymbolAddress((void**)&v,    g_v);
    cudaGetSymbolAddress((void**)&attn, g_attn);
    cudaGetSymbolAddress((void**)&ct,   g_cos);
    cudaGetSymbolAddress((void**)&st,   g_sin);

    // QKV projections
    sgemm_kernel<<<dim3((NH_ * HD_) / GTN, MROWS / GTM), 256>>>(
        hidden, Wq, q, MROWS, NH_ * HD_, 1024);
    sgemm_kernel<<<dim3((NKV_ * HD_) / GTN, MROWS / GTM), 256>>>(
        hidden, Wk, k, MROWS, NKV_ * HD_, 1024);
    sgemm_kernel<<<dim3((NKV_ * HD_) / GTN, MROWS / GTM), 256>>>(
        hidden, Wv, v, MROWS, NKV_ * HD_, 1024);

    // RoPE table + RMSNorm/RoPE
    rope_table_kernel<<<(S_ * 64 + 255) / 256, 256>>>(pos, ct, st);
    {
        int total_warps = B_ * S_ * (NH_ + NKV_);   // 98304
        norm_rope_kernel<<<total_warps / 8, 256>>>(q, k, qw, kw, ct, st);
    }

    // attention
    {
        size_t smem = (size_t)(2 * 64 * 132 + 64 * 64) * sizeof(float); // 83968 B
        cudaFuncSetAttribute(attn_kernel,
                             cudaFuncAttributeMaxDynamicSharedMemorySize,
                             (int)smem);
        attn_kernel<<<dim3(S_ / 64, B_ * NH_), 128, smem>>>(q, k, v, attn);
    }

    // output projection
    sgemm_kernel<<<dim3(1024 / GTN, MROWS / GTM), 256>>>(
        attn, Wo, out, MROWS, 1024, NH_ * HD_);
}

// round 4
// speedup vs baseline: 1.4099x; 1.3548x over previous
#include <cuda_runtime.h>
#include <cuda_bf16.h>
#include <math.h>
#include <stdint.h>

#define B_   2
#define S_   2048
#define NH_  16
#define NKV_ 8
#define HD_  128
#define MROWS (B_ * S_)          // 4096

// ---------------- scratch (device globals; no allocation allowed) ----------
__device__ float g_q[(size_t)B_ * S_ * NH_ * HD_];
__device__ float g_k[(size_t)B_ * S_ * NKV_ * HD_];
__device__ float g_v[(size_t)B_ * S_ * NKV_ * HD_];
__device__ float g_attn[(size_t)B_ * S_ * NH_ * HD_];
__device__ float g_cos[S_ * 64];
__device__ float g_sin[S_ * 64];

// ---------------- packed f32x2 helpers (attention kernel) ------------------
typedef unsigned long long u64;

__device__ __forceinline__ void ffma2(u64& d, u64 a, u64 b) {
    asm("fma.rn.f32x2 %0, %1, %2, %0;" : "+l"(d) : "l"(a), "l"(b));
}
__device__ __forceinline__ void fmul2(u64& d, u64 a, u64 b) {
    asm("mul.rn.f32x2 %0, %1, %2;" : "=l"(d) : "l"(a), "l"(b));
}
__device__ __forceinline__ u64 pack_dup(float x) {
    u64 r;
    asm("mov.b64 %0, {%1, %1};" : "=l"(r) : "f"(x));
    return r;
}
__device__ __forceinline__ float2 unpack2(u64 p) {
    float lo, hi;
    asm("mov.b64 {%0, %1}, %2;" : "=f"(lo), "=f"(hi) : "l"(p));
    return make_float2(lo, hi);
}

// ---------------- mma.sync helpers (baseline PTX, no 'a' features) ---------
__device__ __forceinline__ uint32_t smem_u32(const void* p) {
    uint32_t a;
    asm("{ .reg .u64 t; cvta.to.shared.u64 t, %1; cvt.u32.u64 %0, t; }"
        : "=r"(a) : "l"(p));
    return a;
}

__device__ __forceinline__ void ldsm4(uint32_t* r, uint32_t addr) {
    asm volatile("ldmatrix.sync.aligned.m8n8.x4.shared.b16 {%0,%1,%2,%3}, [%4];"
                 : "=r"(r[0]), "=r"(r[1]), "=r"(r[2]), "=r"(r[3]) : "r"(addr));
}

__device__ __forceinline__ void mma16816(float* c, const uint32_t* a,
                                         uint32_t b0, uint32_t b1) {
    asm volatile(
        "mma.sync.aligned.m16n8k16.row.col.f32.bf16.bf16.f32 "
        "{%0,%1,%2,%3}, {%4,%5,%6,%7}, {%8,%9}, {%0,%1,%2,%3};"
        : "+f"(c[0]), "+f"(c[1]), "+f"(c[2]), "+f"(c[3])
        : "r"(a[0]), "r"(a[1]), "r"(a[2]), "r"(a[3]), "r"(b0), "r"(b1));
}

__device__ __forceinline__ void sts128(uint32_t addr, uint32_t a, uint32_t b,
                                       uint32_t c, uint32_t d) {
    asm volatile("st.shared.v4.b32 [%0], {%1, %2, %3, %4};"
                 :: "r"(addr), "r"(a), "r"(b), "r"(c), "r"(d));
}

// split two fp32 into bf16 hi-pair and lo-pair (packed bf16x2)
__device__ __forceinline__ void split2(float a, float b, uint32_t& hi, uint32_t& lo) {
    asm("cvt.rn.bf16x2.f32 %0, %1, %2;" : "=r"(hi) : "f"(b), "f"(a));
    float ha = __uint_as_float(hi << 16);
    float hb = __uint_as_float(hi & 0xffff0000u);
    float la = a - ha;
    float lb = b - hb;
    asm("cvt.rn.bf16x2.f32 %0, %1, %2;" : "=r"(lo) : "f"(lb), "f"(la));
}

// ============================================================================
// mma.sync GEMM: C[M,N] = A[M,K] @ B[K,N] (row-major fp32 in/out).
// bf16 3-term split: C = Ah*Bh + Al*Bh + Ah*Bl.
// CTA tile 128x128, KC=32, double-buffered SMEM, 256 threads (8 warps),
// warp tile 64x32 (4x4 m16n8k16 tiles).
// SMEM stage layout (stride 40 bf16 = 80B/row, 16B-aligned, ldmatrix
// conflict-free): Ah@0 (10240B) Al@10240 Bh@20480 Bl@30720; stage=40960B.
// ============================================================================
#define KC 32

__global__ __launch_bounds__(256, 1)
void mma_gemm_kernel(const float* __restrict__ A, const float* __restrict__ B,
                     float* __restrict__ C, int M, int N, int K) {
    extern __shared__ __align__(16) char dsm[];

    const int tid  = threadIdx.x;
    const int lane = tid & 31;
    const int wid  = tid >> 5;
    const int m0 = blockIdx.y * 128;
    const int n0 = blockIdx.x * 128;
    const int wm = (wid >> 2) * 64;   // warp m offset in tile
    const int wn = (wid & 3) * 32;    // warp n offset in tile

    const uint32_t sbase = smem_u32(dsm);

    float acc[4][4][4];
#pragma unroll
    for (int i = 0; i < 4; i++)
#pragma unroll
        for (int j = 0; j < 4; j++)
#pragma unroll
            for (int r = 0; r < 4; r++) acc[i][j][r] = 0.0f;

    // loader indices
    const int ar  = tid >> 1;           // A row 0..127
    const int akh = (tid & 1) << 4;     // A k-half 0/16
    const int bn  = tid & 127;          // B n 0..127
    const int bkg = (tid >> 7) << 4;    // B k-group 0/16

    float aregs[16], bregs[16];
    const int nch = K / KC;

    // ---- load chunk 0
    {
        const float* ap = A + (size_t)(m0 + ar) * K + akh;
#pragma unroll
        for (int j = 0; j < 4; j++)
            *(float4*)&aregs[j * 4] = *(const float4*)(ap + j * 4);
        const float* bp = B + (size_t)bkg * N + n0 + bn;
#pragma unroll
        for (int j = 0; j < 16; j++) bregs[j] = bp[(size_t)j * N];
    }
    // ---- store stage 0
    {
        const uint32_t st = sbase;
        uint32_t h[8], l[8];
#pragma unroll
        for (int j = 0; j < 8; j++) split2(aregs[2 * j], aregs[2 * j + 1], h[j], l[j]);
        uint32_t ao = st + (uint32_t)(ar * 80 + akh * 2);
        sts128(ao, h[0], h[1], h[2], h[3]);
        sts128(ao + 16, h[4], h[5], h[6], h[7]);
        sts128(ao + 10240, l[0], l[1], l[2], l[3]);
        sts128(ao + 10256, l[4], l[5], l[6], l[7]);
#pragma unroll
        for (int j = 0; j < 8; j++) split2(bregs[2 * j], bregs[2 * j + 1], h[j], l[j]);
        uint32_t bo = st + 20480u + (uint32_t)(bn * 80 + bkg * 2);
        sts128(bo, h[0], h[1], h[2], h[3]);
        sts128(bo + 16, h[4], h[5], h[6], h[7]);
        sts128(bo + 10240, l[0], l[1], l[2], l[3]);
        sts128(bo + 10256, l[4], l[5], l[6], l[7]);
    }

    for (int c = 0; c < nch; c++) {
        const bool more = (c + 1 < nch);
        if (more) {  // issue global loads for next chunk
            const float* ap = A + (size_t)(m0 + ar) * K + (c + 1) * KC + akh;
#pragma unroll
            for (int j = 0; j < 4; j++)
                *(float4*)&aregs[j * 4] = *(const float4*)(ap + j * 4);
            const float* bp = B + (size_t)((c + 1) * KC + bkg) * N + n0 + bn;
#pragma unroll
            for (int j = 0; j < 16; j++) bregs[j] = bp[(size_t)j * N];
        }
        __syncthreads();
        if (more) {  // store next chunk into the other stage
            const uint32_t st = sbase + (uint32_t)(((c + 1) & 1) * 40960);
            uint32_t h[8], l[8];
#pragma unroll
            for (int j = 0; j < 8; j++) split2(aregs[2 * j], aregs[2 * j + 1], h[j], l[j]);
            uint32_t ao = st + (uint32_t)(ar * 80 + akh * 2);
            sts128(ao, h[0], h[1], h[2], h[3]);
            sts128(ao + 16, h[4], h[5], h[6], h[7]);
            sts128(ao + 10240, l[0], l[1], l[2], l[3]);
            sts128(ao + 10256, l[4], l[5], l[6], l[7]);
#pragma unroll
            for (int j = 0; j < 8; j++) split2(bregs[2 * j], bregs[2 * j + 1], h[j], l[j]);
            uint32_t bo = st + 20480u + (uint32_t)(bn * 80 + bkg * 2);
            sts128(bo, h[0], h[1], h[2], h[3]);
            sts128(bo + 16, h[4], h[5], h[6], h[7]);
            sts128(bo + 10240, l[0], l[1], l[2], l[3]);
            sts128(bo + 10256, l[4], l[5], l[6], l[7]);
        }
        // ---- compute on stage c&1
        {
            const uint32_t st = sbase + (uint32_t)((c & 1) * 40960);
#pragma unroll
            for (int ks = 0; ks < KC; ks += 16) {
                uint32_t ah[4][4], al[4][4], bh[2][4], bl[2][4];
                const uint32_t arow = (uint32_t)(wm + (lane & 15));
                const uint32_t acol = (uint32_t)(ks + ((lane >> 4) << 3));
#pragma unroll
                for (int mt = 0; mt < 4; mt++) {
                    uint32_t ad = st + (arow + mt * 16) * 80 + acol * 2;
                    ldsm4(ah[mt], ad);
                    ldsm4(al[mt], ad + 10240);
                }
                const uint32_t brow =
                    (uint32_t)(wn + (lane & 7) + ((lane >> 4) << 3));
                const uint32_t bcol = (uint32_t)(ks + (lane & 8));
#pragma unroll
                for (int bt = 0; bt < 2; bt++) {
                    uint32_t bd = st + 20480u + (brow + bt * 16) * 80 + bcol * 2;
                    ldsm4(bh[bt], bd);
                    ldsm4(bl[bt], bd + 10240);
                }
#pragma unroll
                for (int mt = 0; mt < 4; mt++)
#pragma unroll
                    for (int nt = 0; nt < 4; nt++) {
                        const uint32_t* bhp = &bh[nt >> 1][(nt & 1) * 2];
                        const uint32_t* blp = &bl[nt >> 1][(nt & 1) * 2];
                        mma16816(acc[mt][nt], ah[mt], bhp[0], bhp[1]);
                        mma16816(acc[mt][nt], al[mt], bhp[0], bhp[1]);
                        mma16816(acc[mt][nt], ah[mt], blp[0], blp[1]);
                    }
            }
        }
    }

    // ---- epilogue
#pragma unroll
    for (int mt = 0; mt < 4; mt++)
#pragma unroll
        for (int nt = 0; nt < 4; nt++) {
            int row = m0 + wm + mt * 16 + (lane >> 2);
            int col = n0 + wn + nt * 8 + (lane & 3) * 2;
            *(float2*)&C[(size_t)row * N + col] =
                make_float2(acc[mt][nt][0], acc[mt][nt][1]);
            *(float2*)&C[(size_t)(row + 8) * N + col] =
                make_float2(acc[mt][nt][2], acc[mt][nt][3]);
        }
}

// ============================================================================
// RoPE cos/sin table: [S, 64]
// ============================================================================
__global__ void rope_table_kernel(const int* __restrict__ pos,
                                  float* __restrict__ ctab,
                                  float* __restrict__ stab) {
    int idx = blockIdx.x * blockDim.x + threadIdx.x;
    if (idx >= S_ * 64) return;
    int s  = idx >> 6;
    int fi = idx & 63;
    float inv = (float)exp(-13.815510557964274 * (double)fi / 64.0);
    float ang = (float)pos[s] * inv;
    float c, sn;
    sincosf(ang, &sn, &c);
    ctab[idx] = c;
    stab[idx] = sn;
}

// ============================================================================
// RMSNorm + RoPE in-place over g_q and g_k.
// ============================================================================
__global__ void norm_rope_kernel(float* __restrict__ q, float* __restrict__ k,
                                 const float* __restrict__ qw,
                                 const float* __restrict__ kw,
                                 const float* __restrict__ ctab,
                                 const float* __restrict__ stab) {
    const int warp = (blockIdx.x * blockDim.x + threadIdx.x) >> 5;
    const int lane = threadIdx.x & 31;
    const int QROWS = B_ * S_ * NH_;

    float* ptr;
    const float* w;
    int s;
    if (warp < QROWS) {
        ptr = q + (size_t)warp * HD_;
        w = qw;
        s = (warp / NH_) % S_;
    } else {
        int r = warp - QROWS;
        ptr = k + (size_t)r * HD_;
        w = kw;
        s = (r / NKV_) % S_;
    }

    float4 x = ((const float4*)ptr)[lane];
    float ss = x.x * x.x + x.y * x.y + x.z * x.z + x.w * x.w;
#pragma unroll
    for (int off = 16; off; off >>= 1)
        ss += __shfl_xor_sync(0xffffffffu, ss, off);
    float rms = rsqrtf(ss * (1.0f / 128.0f) + 1e-6f);

    const int d0 = lane * 4;
    float xn[4];
    xn[0] = x.x * rms * w[d0 + 0];
    xn[1] = x.y * rms * w[d0 + 1];
    xn[2] = x.z * rms * w[d0 + 2];
    xn[3] = x.w * rms * w[d0 + 3];

    float out[4];
#pragma unroll
    for (int j = 0; j < 4; j++) {
        int fi = (d0 + j) & 63;
        float c  = ctab[s * 64 + fi];
        float sn = stab[s * 64 + fi];
        float partner = __shfl_xor_sync(0xffffffffu, xn[j], 16);
        out[j] = (lane < 16) ? (xn[j] * c - partner * sn)
                             : (xn[j] * c + partner * sn);
    }
    ((float4*)ptr)[lane] = make_float4(out[0], out[1], out[2], out[3]);
}

// ============================================================================
// Flash attention, fp32, causal, GQA. FFMA2 inner loops. (proven R2 version)
// ============================================================================
__global__ __launch_bounds__(128, 2)
void attn_kernel(const float* __restrict__ q, const float* __restrict__ k,
                 const float* __restrict__ v, float* __restrict__ o) {
    extern __shared__ float sm[];
    float* Qs  = sm;
    float* KVs = sm + 64 * 132;
    float* Ps  = sm + 2 * 64 * 132;

    const int tid = threadIdx.x;
    const int bh = blockIdx.y;
    const int b  = bh >> 4;
    const int h  = bh & 15;
    const int hk = h >> 1;
    const int qtile = gridDim.x - 1 - blockIdx.x;
    const int q0 = qtile * 64;
    const float scale = 0.08838834764831845f;

#pragma unroll
    for (int t = 0; t < 16; t++) {
        int idx = t * 128 + tid;
        int r  = idx >> 5;
        int d4 = (idx & 31) << 2;
        float4 qv = *(const float4*)
            &q[((size_t)(b * S_ + q0 + r) * NH_ + h) * HD_ + d4];
        *(float4*)&Qs[r * 132 + d4] =
            make_float4(qv.x * scale, qv.y * scale, qv.z * scale, qv.w * scale);
    }

    const int trow = tid >> 4;
    const int tcol = tid & 15;

    float m_i[8], l_i[8];
    u64 acc2[8][4];
#pragma unroll
    for (int i = 0; i < 8; i++) {
        m_i[i] = -1e30f;
        l_i[i] = 0.0f;
#pragma unroll
        for (int j = 0; j < 4; j++) acc2[i][j] = 0ULL;
    }

    for (int kt = 0; kt <= qtile; kt++) {
        const int k0 = kt * 64;
        __syncthreads();

#pragma unroll
        for (int t = 0; t < 16; t++) {
            int idx = t * 128 + tid;
            int r  = idx >> 5;
            int d4 = (idx & 31) << 2;
            *(float4*)&KVs[r * 132 + d4] = *(const float4*)
                &k[((size_t)(b * S_ + k0 + r) * NKV_ + hk) * HD_ + d4];
        }
        __syncthreads();

        u64 sc2[8][4];
#pragma unroll
        for (int i = 0; i < 8; i++)
#pragma unroll
            for (int j = 0; j < 4; j++) sc2[i][j] = 0ULL;

        for (int d4 = 0; d4 < 128; d4 += 4) {
            ulonglong2 kv2[4];
#pragma unroll
            for (int j = 0; j < 4; j++)
                kv2[j] = *(const ulonglong2*)&KVs[(tcol * 4 + j) * 132 + d4];
#pragma unroll
            for (int i = 0; i < 8; i++) {
                ulonglong2 qv2 = *(const ulonglong2*)&Qs[(trow * 8 + i) * 132 + d4];
#pragma unroll
                for (int j = 0; j < 4; j++) {
                    ffma2(sc2[i][j], qv2.x, kv2[j].x);
                    ffma2(sc2[i][j], qv2.y, kv2[j].y);
                }
            }
        }

        float sc[8][4];
#pragma unroll
        for (int i = 0; i < 8; i++)
#pragma unroll
            for (int j = 0; j < 4; j++) {
                float2 p = unpack2(sc2[i][j]);
                sc[i][j] = p.x + p.y;
            }

        if (kt == qtile) {
#pragma unroll
            for (int i = 0; i < 8; i++)
#pragma unroll
                for (int j = 0; j < 4; j++)
                    if (tcol * 4 + j > trow * 8 + i) sc[i][j] = -1e30f;
        }

        float p_[8][4];
#pragma unroll
        for (int i = 0; i < 8; i++) {
            float mx = fmaxf(fmaxf(sc[i][0], sc[i][1]), fmaxf(sc[i][2], sc[i][3]));
#pragma unroll
            for (int off = 8; off; off >>= 1)
                mx = fmaxf(mx, __shfl_xor_sync(0xffffffffu, mx, off));
            float mn = fmaxf(m_i[i], mx);
            float alpha = __expf(m_i[i] - mn);
            float rs = 0.0f;
#pragma unroll
            for (int j = 0; j < 4; j++) {
                p_[i][j] = __expf(sc[i][j] - mn);
                rs += p_[i][j];
            }
#pragma unroll
            for (int off = 8; off; off >>= 1)
                rs += __shfl_xor_sync(0xffffffffu, rs, off);
            l_i[i] = l_i[i] * alpha + rs;
            m_i[i] = mn;
            u64 al2 = pack_dup(alpha);
#pragma unroll
            for (int jj = 0; jj < 4; jj++) fmul2(acc2[i][jj], acc2[i][jj], al2);
        }

        __syncthreads();

#pragma unroll
        for (int i = 0; i < 8; i++)
            *(float4*)&Ps[(trow * 8 + i) * 64 + tcol * 4] =
                make_float4(p_[i][0], p_[i][1], p_[i][2], p_[i][3]);
#pragma unroll
        for (int t = 0; t < 16; t++) {
            int idx = t * 128 + tid;
            int r  = idx >> 5;
            int d4 = (idx & 31) << 2;
            *(float4*)&KVs[r * 132 + d4] = *(const float4*)
                &v[((size_t)(b * S_ + k0 + r) * NKV_ + hk) * HD_ + d4];
        }
        __syncthreads();

        for (int n4 = 0; n4 < 64; n4 += 4) {
            float pr[8][4];
#pragma unroll
            for (int i = 0; i < 8; i++) {
                float4 t4 = *(const float4*)&Ps[(trow * 8 + i) * 64 + n4];
                pr[i][0] = t4.x; pr[i][1] = t4.y; pr[i][2] = t4.z; pr[i][3] = t4.w;
            }
#pragma unroll
            for (int u = 0; u < 4; u++) {
                ulonglong2 v01 = *(const ulonglong2*)&KVs[(n4 + u) * 132 + tcol * 8];
                ulonglong2 v23 = *(const ulonglong2*)&KVs[(n4 + u) * 132 + tcol * 8 + 4];
#pragma unroll
                for (int i = 0; i < 8; i++) {
                    u64 pw2 = pack_dup(pr[i][u]);
                    ffma2(acc2[i][0], pw2, v01.x);
                    ffma2(acc2[i][1], pw2, v01.y);
                    ffma2(acc2[i][2], pw2, v23.x);
                    ffma2(acc2[i][3], pw2, v23.y);
                }
            }
        }
    }

#pragma unroll
    for (int i = 0; i < 8; i++) {
        u64 inv2 = pack_dup(1.0f / l_i[i]);
        float* op = &o[((size_t)(b * S_ + q0 + trow * 8 + i) * NH_ + h) * HD_ +
                       tcol * 8];
#pragma unroll
        for (int j = 0; j < 4; j++) {
            u64 r;
            fmul2(r, acc2[i][j], inv2);
            ((u64*)op)[j] = r;
        }
    }
}

// ============================================================================
// launch
// ============================================================================
extern "C" void kernel_launch(void* const* d_in, const int* in_sizes, int n_in,
                              void* d_out, int out_size) {
    const float* hidden = (const float*)d_in[0];
    const int*   pos    = (const int*)d_in[1];
    const float* Wq     = (const float*)d_in[2];
    const float* Wk     = (const float*)d_in[3];
    const float* Wv     = (const float*)d_in[4];
    const float* Wo     = (const float*)d_in[5];
    const float* qw     = (const float*)d_in[6];
    const float* kw     = (const float*)d_in[7];
    float* out = (float*)d_out;

    float *q, *k, *v, *attn, *ct, *st;
    cudaGetSymbolAddress((void**)&q,    g_q);
    cudaGetSymbolAddress((void**)&k,    g_k);
    cudaGetSymbolAddress((void**)&v,    g_v);
    cudaGetSymbolAddress((void**)&attn, g_attn);
    cudaGetSymbolAddress((void**)&ct,   g_cos);
    cudaGetSymbolAddress((void**)&st,   g_sin);

    const int gemm_smem = 2 * 40960;  // 80 KB
    cudaFuncSetAttribute(mma_gemm_kernel,
                         cudaFuncAttributeMaxDynamicSharedMemorySize, gemm_smem);

    // QKV projections (mma.sync bf16 x3)
    mma_gemm_kernel<<<dim3(2048 / 128, MROWS / 128), 256, gemm_smem>>>(
        hidden, Wq, q, MROWS, 2048, 1024);
    mma_gemm_kernel<<<dim3(1024 / 128, MROWS / 128), 256, gemm_smem>>>(
        hidden, Wk, k, MROWS, 1024, 1024);
    mma_gemm_kernel<<<dim3(1024 / 128, MROWS / 128), 256, gemm_smem>>>(
        hidden, Wv, v, MROWS, 1024, 1024);

    // RoPE table + RMSNorm/RoPE
    rope_table_kernel<<<(S_ * 64 + 255) / 256, 256>>>(pos, ct, st);
    {
        int total_warps = B_ * S_ * (NH_ + NKV_);
        norm_rope_kernel<<<total_warps / 8, 256>>>(q, k, qw, kw, ct, st);
    }

    // attention
    {
        size_t smem = (size_t)(2 * 64 * 132 + 64 * 64) * sizeof(float);
        cudaFuncSetAttribute(attn_kernel,
                             cudaFuncAttributeMaxDynamicSharedMemorySize,
                             (int)smem);
        attn_kernel<<<dim3(S_ / 64, B_ * NH_), 128, smem>>>(q, k, v, attn);
    }

    // output projection (mma.sync bf16 x3)
    mma_gemm_kernel<<<dim3(1024 / 128, MROWS / 128), 256, gemm_smem>>>(
        attn, Wo, out, MROWS, 1024, 2048);
}

// round 5
// speedup vs baseline: 2.4295x; 1.7232x over previous
#include <cuda_runtime.h>
#include <cuda_bf16.h>
#include <math.h>
#include <stdint.h>

#define B_   2
#define S_   2048
#define NH_  16
#define NKV_ 8
#define HD_  128
#define MROWS (B_ * S_)          // 4096

// ---------------- scratch (device globals; no allocation allowed) ----------
__device__ float g_q[(size_t)B_ * S_ * NH_ * HD_];
__device__ float g_k[(size_t)B_ * S_ * NKV_ * HD_];
__device__ float g_v[(size_t)B_ * S_ * NKV_ * HD_];
__device__ float g_attn[(size_t)B_ * S_ * NH_ * HD_];
__device__ float g_cos[S_ * 64];
__device__ float g_sin[S_ * 64];

// ---------------- mma.sync helpers (baseline PTX, no 'a' features) ---------
__device__ __forceinline__ uint32_t smem_u32(const void* p) {
    uint32_t a;
    asm("{ .reg .u64 t; cvta.to.shared.u64 t, %1; cvt.u32.u64 %0, t; }"
        : "=r"(a) : "l"(p));
    return a;
}

__device__ __forceinline__ void ldsm4(uint32_t* r, uint32_t addr) {
    asm volatile("ldmatrix.sync.aligned.m8n8.x4.shared.b16 {%0,%1,%2,%3}, [%4];"
                 : "=r"(r[0]), "=r"(r[1]), "=r"(r[2]), "=r"(r[3]) : "r"(addr));
}
__device__ __forceinline__ void ldsm4t(uint32_t* r, uint32_t addr) {
    asm volatile("ldmatrix.sync.aligned.m8n8.x4.trans.shared.b16 {%0,%1,%2,%3}, [%4];"
                 : "=r"(r[0]), "=r"(r[1]), "=r"(r[2]), "=r"(r[3]) : "r"(addr));
}

__device__ __forceinline__ void mma16816(float* c, const uint32_t* a,
                                         uint32_t b0, uint32_t b1) {
    asm volatile(
        "mma.sync.aligned.m16n8k16.row.col.f32.bf16.bf16.f32 "
        "{%0,%1,%2,%3}, {%4,%5,%6,%7}, {%8,%9}, {%0,%1,%2,%3};"
        : "+f"(c[0]), "+f"(c[1]), "+f"(c[2]), "+f"(c[3])
        : "r"(a[0]), "r"(a[1]), "r"(a[2]), "r"(a[3]), "r"(b0), "r"(b1));
}

__device__ __forceinline__ void sts128(uint32_t addr, uint32_t a, uint32_t b,
                                       uint32_t c, uint32_t d) {
    asm volatile("st.shared.v4.b32 [%0], {%1, %2, %3, %4};"
                 :: "r"(addr), "r"(a), "r"(b), "r"(c), "r"(d));
}

// split two fp32 into bf16 hi-pair and lo-pair (packed bf16x2)
__device__ __forceinline__ void split2(float a, float b, uint32_t& hi, uint32_t& lo) {
    asm("cvt.rn.bf16x2.f32 %0, %1, %2;" : "=r"(hi) : "f"(b), "f"(a));
    float ha = __uint_as_float(hi << 16);
    float hb = __uint_as_float(hi & 0xffff0000u);
    float la = a - ha;
    float lb = b - hb;
    asm("cvt.rn.bf16x2.f32 %0, %1, %2;" : "=r"(lo) : "f"(lb), "f"(la));
}

// fast 2^y on the FMA pipe (no MUFU). |rel err| ~3e-6 for y <= 0.
__device__ __forceinline__ float exp2fast(float y) {
    y = fmaxf(y, -126.0f);
    float r = y + 12582912.0f;          // round-to-int magic (1.5*2^23)
    float kf = r - 12582912.0f;
    float f = y - kf;                   // f in [-0.5, 0.5]
    float p = 1.3333558146e-3f;
    p = fmaf(p, f, 9.6181291076e-3f);
    p = fmaf(p, f, 5.5504108664e-2f);
    p = fmaf(p, f, 2.4022650696e-1f);
    p = fmaf(p, f, 6.9314718056e-1f);
    p = fmaf(p, f, 1.0f);
    return __int_as_float(__float_as_int(p) + (__float_as_int(r) << 23));
}

// ============================================================================
// mma.sync GEMM (unchanged from R4 — proven)
// ============================================================================
#define KC 32

__global__ __launch_bounds__(256, 1)
void mma_gemm_kernel(const float* __restrict__ A, const float* __restrict__ B,
                     float* __restrict__ C, int M, int N, int K) {
    extern __shared__ __align__(16) char dsm[];

    const int tid  = threadIdx.x;
    const int lane = tid & 31;
    const int wid  = tid >> 5;
    const int m0 = blockIdx.y * 128;
    const int n0 = blockIdx.x * 128;
    const int wm = (wid >> 2) * 64;
    const int wn = (wid & 3) * 32;

    const uint32_t sbase = smem_u32(dsm);

    float acc[4][4][4];
#pragma unroll
    for (int i = 0; i < 4; i++)
#pragma unroll
        for (int j = 0; j < 4; j++)
#pragma unroll
            for (int r = 0; r < 4; r++) acc[i][j][r] = 0.0f;

    const int ar  = tid >> 1;
    const int akh = (tid & 1) << 4;
    const int bn  = tid & 127;
    const int bkg = (tid >> 7) << 4;

    float aregs[16], bregs[16];
    const int nch = K / KC;

    {
        const float* ap = A + (size_t)(m0 + ar) * K + akh;
#pragma unroll
        for (int j = 0; j < 4; j++)
            *(float4*)&aregs[j * 4] = *(const float4*)(ap + j * 4);
        const float* bp = B + (size_t)bkg * N + n0 + bn;
#pragma unroll
        for (int j = 0; j < 16; j++) bregs[j] = bp[(size_t)j * N];
    }
    {
        const uint32_t st = sbase;
        uint32_t h[8], l[8];
#pragma unroll
        for (int j = 0; j < 8; j++) split2(aregs[2 * j], aregs[2 * j + 1], h[j], l[j]);
        uint32_t ao = st + (uint32_t)(ar * 80 + akh * 2);
        sts128(ao, h[0], h[1], h[2], h[3]);
        sts128(ao + 16, h[4], h[5], h[6], h[7]);
        sts128(ao + 10240, l[0], l[1], l[2], l[3]);
        sts128(ao + 10256, l[4], l[5], l[6], l[7]);
#pragma unroll
        for (int j = 0; j < 8; j++) split2(bregs[2 * j], bregs[2 * j + 1], h[j], l[j]);
        uint32_t bo = st + 20480u + (uint32_t)(bn * 80 + bkg * 2);
        sts128(bo, h[0], h[1], h[2], h[3]);
        sts128(bo + 16, h[4], h[5], h[6], h[7]);
        sts128(bo + 10240, l[0], l[1], l[2], l[3]);
        sts128(bo + 10256, l[4], l[5], l[6], l[7]);
    }

    for (int c = 0; c < nch; c++) {
        const bool more = (c + 1 < nch);
        if (more) {
            const float* ap = A + (size_t)(m0 + ar) * K + (c + 1) * KC + akh;
#pragma unroll
            for (int j = 0; j < 4; j++)
                *(float4*)&aregs[j * 4] = *(const float4*)(ap + j * 4);
            const float* bp = B + (size_t)((c + 1) * KC + bkg) * N + n0 + bn;
#pragma unroll
            for (int j = 0; j < 16; j++) bregs[j] = bp[(size_t)j * N];
        }
        __syncthreads();
        if (more) {
            const uint32_t st = sbase + (uint32_t)(((c + 1) & 1) * 40960);
            uint32_t h[8], l[8];
#pragma unroll
            for (int j = 0; j < 8; j++) split2(aregs[2 * j], aregs[2 * j + 1], h[j], l[j]);
            uint32_t ao = st + (uint32_t)(ar * 80 + akh * 2);
            sts128(ao, h[0], h[1], h[2], h[3]);
            sts128(ao + 16, h[4], h[5], h[6], h[7]);
            sts128(ao + 10240, l[0], l[1], l[2], l[3]);
            sts128(ao + 10256, l[4], l[5], l[6], l[7]);
#pragma unroll
            for (int j = 0; j < 8; j++) split2(bregs[2 * j], bregs[2 * j + 1], h[j], l[j]);
            uint32_t bo = st + 20480u + (uint32_t)(bn * 80 + bkg * 2);
            sts128(bo, h[0], h[1], h[2], h[3]);
            sts128(bo + 16, h[4], h[5], h[6], h[7]);
            sts128(bo + 10240, l[0], l[1], l[2], l[3]);
            sts128(bo + 10256, l[4], l[5], l[6], l[7]);
        }
        {
            const uint32_t st = sbase + (uint32_t)((c & 1) * 40960);
#pragma unroll
            for (int ks = 0; ks < KC; ks += 16) {
                uint32_t ah[4][4], al[4][4], bh[2][4], bl[2][4];
                const uint32_t arow = (uint32_t)(wm + (lane & 15));
                const uint32_t acol = (uint32_t)(ks + ((lane >> 4) << 3));
#pragma unroll
                for (int mt = 0; mt < 4; mt++) {
                    uint32_t ad = st + (arow + mt * 16) * 80 + acol * 2;
                    ldsm4(ah[mt], ad);
                    ldsm4(al[mt], ad + 10240);
                }
                const uint32_t brow =
                    (uint32_t)(wn + (lane & 7) + ((lane >> 4) << 3));
                const uint32_t bcol = (uint32_t)(ks + (lane & 8));
#pragma unroll
                for (int bt = 0; bt < 2; bt++) {
                    uint32_t bd = st + 20480u + (brow + bt * 16) * 80 + bcol * 2;
                    ldsm4(bh[bt], bd);
                    ldsm4(bl[bt], bd + 10240);
                }
#pragma unroll
                for (int mt = 0; mt < 4; mt++)
#pragma unroll
                    for (int nt = 0; nt < 4; nt++) {
                        const uint32_t* bhp = &bh[nt >> 1][(nt & 1) * 2];
                        const uint32_t* blp = &bl[nt >> 1][(nt & 1) * 2];
                        mma16816(acc[mt][nt], ah[mt], bhp[0], bhp[1]);
                        mma16816(acc[mt][nt], al[mt], bhp[0], bhp[1]);
                        mma16816(acc[mt][nt], ah[mt], blp[0], blp[1]);
                    }
            }
        }
    }

#pragma unroll
    for (int mt = 0; mt < 4; mt++)
#pragma unroll
        for (int nt = 0; nt < 4; nt++) {
            int row = m0 + wm + mt * 16 + (lane >> 2);
            int col = n0 + wn + nt * 8 + (lane & 3) * 2;
            *(float2*)&C[(size_t)row * N + col] =
                make_float2(acc[mt][nt][0], acc[mt][nt][1]);
            *(float2*)&C[(size_t)(row + 8) * N + col] =
                make_float2(acc[mt][nt][2], acc[mt][nt][3]);
        }
}

// ============================================================================
// RoPE cos/sin table
// ============================================================================
__global__ void rope_table_kernel(const int* __restrict__ pos,
                                  float* __restrict__ ctab,
                                  float* __restrict__ stab) {
    int idx = blockIdx.x * blockDim.x + threadIdx.x;
    if (idx >= S_ * 64) return;
    int s  = idx >> 6;
    int fi = idx & 63;
    float inv = (float)exp(-13.815510557964274 * (double)fi / 64.0);
    float ang = (float)pos[s] * inv;
    float c, sn;
    sincosf(ang, &sn, &c);
    ctab[idx] = c;
    stab[idx] = sn;
}

// ============================================================================
// RMSNorm + RoPE in-place over g_q and g_k.
// ============================================================================
__global__ void norm_rope_kernel(float* __restrict__ q, float* __restrict__ k,
                                 const float* __restrict__ qw,
                                 const float* __restrict__ kw,
                                 const float* __restrict__ ctab,
                                 const float* __restrict__ stab) {
    const int warp = (blockIdx.x * blockDim.x + threadIdx.x) >> 5;
    const int lane = threadIdx.x & 31;
    const int QROWS = B_ * S_ * NH_;

    float* ptr;
    const float* w;
    int s;
    if (warp < QROWS) {
        ptr = q + (size_t)warp * HD_;
        w = qw;
        s = (warp / NH_) % S_;
    } else {
        int r = warp - QROWS;
        ptr = k + (size_t)r * HD_;
        w = kw;
        s = (r / NKV_) % S_;
    }

    float4 x = ((const float4*)ptr)[lane];
    float ss = x.x * x.x + x.y * x.y + x.z * x.z + x.w * x.w;
#pragma unroll
    for (int off = 16; off; off >>= 1)
        ss += __shfl_xor_sync(0xffffffffu, ss, off);
    float rms = rsqrtf(ss * (1.0f / 128.0f) + 1e-6f);

    const int d0 = lane * 4;
    float xn[4];
    xn[0] = x.x * rms * w[d0 + 0];
    xn[1] = x.y * rms * w[d0 + 1];
    xn[2] = x.z * rms * w[d0 + 2];
    xn[3] = x.w * rms * w[d0 + 3];

    float out[4];
#pragma unroll
    for (int j = 0; j < 4; j++) {
        int fi = (d0 + j) & 63;
        float c  = ctab[s * 64 + fi];
        float sn = stab[s * 64 + fi];
        float partner = __shfl_xor_sync(0xffffffffu, xn[j], 16);
        out[j] = (lane < 16) ? (xn[j] * c - partner * sn)
                             : (xn[j] * c + partner * sn);
    }
    ((float4*)ptr)[lane] = make_float4(out[0], out[1], out[2], out[3]);
}

// ============================================================================
// Flash attention via mma.sync bf16 3-term split + fast base-2 softmax.
// BM=128 (CTA), BN=64 per iteration, 8 warps (16 rows each), causal, GQA.
// SMEM (stride 272B/row, conflict-free for ldmatrix):
//   Qh@0 Ql@34816 | Kh@69632 Kl@87040 | Vh@104448 Vl@121856  => 139264 B.
// ============================================================================
#define ASTRIDE 272

__global__ __launch_bounds__(256, 1)
void attn_mma_kernel(const float* __restrict__ qg, const float* __restrict__ kg,
                     const float* __restrict__ vg, float* __restrict__ og) {
    extern __shared__ __align__(16) char asmem[];
    const uint32_t sb = smem_u32(asmem);
    const uint32_t Qh = sb, Ql = sb + 34816u;
    const uint32_t Kh = sb + 69632u, Kl = sb + 87040u;
    const uint32_t Vh = sb + 104448u, Vl = sb + 121856u;

    const int tid = threadIdx.x;
    const int lane = tid & 31;
    const int wid = tid >> 5;
    const int bh = blockIdx.y;
    const int b  = bh >> 4;
    const int h  = bh & 15;
    const int hk = h >> 1;
    const int qt = gridDim.x - 1 - blockIdx.x;   // heavy tiles first
    const int q0 = qt * 128;
    const int wr = wid * 16;                     // warp's row offset
    const float qscale = 0.1275174985f;          // 1/sqrt(128) * log2(e)

    // ---- load Q tile (pre-scaled, split hi/lo)
    {
        const int r = tid >> 1;
        const int hf = (tid & 1) * 64;
        const float* qp = &qg[((size_t)(b * S_ + q0 + r) * NH_ + h) * HD_ + hf];
        const uint32_t off = (uint32_t)(r * ASTRIDE + hf * 2);
#pragma unroll
        for (int j = 0; j < 8; j++) {
            float4 x0 = ((const float4*)qp)[2 * j];
            float4 x1 = ((const float4*)qp)[2 * j + 1];
            uint32_t h0, h1, h2, h3, l0, l1, l2, l3;
            split2(x0.x * qscale, x0.y * qscale, h0, l0);
            split2(x0.z * qscale, x0.w * qscale, h1, l1);
            split2(x1.x * qscale, x1.y * qscale, h2, l2);
            split2(x1.z * qscale, x1.w * qscale, h3, l3);
            sts128(Qh + off + j * 16, h0, h1, h2, h3);
            sts128(Ql + off + j * 16, l0, l1, l2, l3);
        }
    }

    float oa[16][4];
    float m_i[2], l_i[2];
#pragma unroll
    for (int nt = 0; nt < 16; nt++)
#pragma unroll
        for (int r = 0; r < 4; r++) oa[nt][r] = 0.0f;
    m_i[0] = m_i[1] = -1e30f;
    l_i[0] = l_i[1] = 0.0f;

    const int nkt = 2 * (qt + 1);
    for (int kt = 0; kt < nkt; kt++) {
        const int k0 = kt * 64;
        __syncthreads();
        // ---- load K,V tiles (split hi/lo)
        {
            const int r = tid >> 2;
            const int qd = (tid & 3) * 32;
            const size_t gro = ((size_t)(b * S_ + k0 + r) * NKV_ + hk) * HD_ + qd;
            const uint32_t off = (uint32_t)(r * ASTRIDE + qd * 2);
            const float* kp = &kg[gro];
            const float* vp = &vg[gro];
#pragma unroll
            for (int j = 0; j < 4; j++) {
                float4 x0 = ((const float4*)kp)[2 * j];
                float4 x1 = ((const float4*)kp)[2 * j + 1];
                uint32_t h0, h1, h2, h3, l0, l1, l2, l3;
                split2(x0.x, x0.y, h0, l0);
                split2(x0.z, x0.w, h1, l1);
                split2(x1.x, x1.y, h2, l2);
                split2(x1.z, x1.w, h3, l3);
                sts128(Kh + off + j * 16, h0, h1, h2, h3);
                sts128(Kl + off + j * 16, l0, l1, l2, l3);
            }
#pragma unroll
            for (int j = 0; j < 4; j++) {
                float4 x0 = ((const float4*)vp)[2 * j];
                float4 x1 = ((const float4*)vp)[2 * j + 1];
                uint32_t h0, h1, h2, h3, l0, l1, l2, l3;
                split2(x0.x, x0.y, h0, l0);
                split2(x0.z, x0.w, h1, l1);
                split2(x1.x, x1.y, h2, l2);
                split2(x1.z, x1.w, h3, l3);
                sts128(Vh + off + j * 16, h0, h1, h2, h3);
                sts128(Vl + off + j * 16, l0, l1, l2, l3);
            }
        }
        __syncthreads();

        // ---- S = Q @ K^T (3-term bf16), S tile 16x64 per warp
        float sc[8][4];
#pragma unroll
        for (int nt = 0; nt < 8; nt++)
#pragma unroll
            for (int r = 0; r < 4; r++) sc[nt][r] = 0.0f;

#pragma unroll
        for (int kc = 0; kc < 8; kc++) {
            const uint32_t aoff =
                (uint32_t)((wr + (lane & 15)) * ASTRIDE +
                           (kc * 16 + ((lane >> 4) << 3)) * 2);
            uint32_t ah[4], al[4];
            ldsm4(ah, Qh + aoff);
            ldsm4(al, Ql + aoff);
            const uint32_t bbase =
                (uint32_t)((((lane >> 4) << 3) + (lane & 7)) * ASTRIDE +
                           (kc * 16 + ((lane >> 3) & 1) * 8) * 2);
#pragma unroll
            for (int bg = 0; bg < 4; bg++) {
                const uint32_t boff = bbase + (uint32_t)(bg * 16 * ASTRIDE);
                uint32_t bh4[4], bl4[4];
                ldsm4(bh4, Kh + boff);
                ldsm4(bl4, Kl + boff);
                mma16816(sc[2 * bg], ah, bh4[0], bh4[1]);
                mma16816(sc[2 * bg], al, bh4[0], bh4[1]);
                mma16816(sc[2 * bg], ah, bl4[0], bl4[1]);
                mma16816(sc[2 * bg + 1], ah, bh4[2], bh4[3]);
                mma16816(sc[2 * bg + 1], al, bh4[2], bh4[3]);
                mma16816(sc[2 * bg + 1], ah, bl4[2], bl4[3]);
            }
        }

        // ---- causal mask (only the two diagonal tiles need it)
        const int row0 = q0 + wr + (lane >> 2);
        const int row1 = row0 + 8;
        if (kt >= 2 * qt) {
#pragma unroll
            for (int nt = 0; nt < 8; nt++) {
                int cb = k0 + nt * 8 + (lane & 3) * 2;
                if (cb > row0) sc[nt][0] = -1e30f;
                if (cb + 1 > row0) sc[nt][1] = -1e30f;
                if (cb > row1) sc[nt][2] = -1e30f;
                if (cb + 1 > row1) sc[nt][3] = -1e30f;
            }
        }

        // ---- online softmax (base-2 domain, poly exp2)
        float mx0 = sc[0][0], mx1 = sc[0][2];
#pragma unroll
        for (int nt = 0; nt < 8; nt++) {
            mx0 = fmaxf(mx0, fmaxf(sc[nt][0], sc[nt][1]));
            mx1 = fmaxf(mx1, fmaxf(sc[nt][2], sc[nt][3]));
        }
        mx0 = fmaxf(mx0, __shfl_xor_sync(0xffffffffu, mx0, 1));
        mx0 = fmaxf(mx0, __shfl_xor_sync(0xffffffffu, mx0, 2));
        mx1 = fmaxf(mx1, __shfl_xor_sync(0xffffffffu, mx1, 1));
        mx1 = fmaxf(mx1, __shfl_xor_sync(0xffffffffu, mx1, 2));
        const float mn0 = fmaxf(m_i[0], mx0);
        const float mn1 = fmaxf(m_i[1], mx1);
        const float alpha0 = exp2fast(m_i[0] - mn0);
        const float alpha1 = exp2fast(m_i[1] - mn1);
        m_i[0] = mn0;
        m_i[1] = mn1;

        float rs0 = 0.0f, rs1 = 0.0f;
#pragma unroll
        for (int nt = 0; nt < 8; nt++) {
            sc[nt][0] = exp2fast(sc[nt][0] - mn0);
            sc[nt][1] = exp2fast(sc[nt][1] - mn0);
            sc[nt][2] = exp2fast(sc[nt][2] - mn1);
            sc[nt][3] = exp2fast(sc[nt][3] - mn1);
            rs0 += sc[nt][0] + sc[nt][1];
            rs1 += sc[nt][2] + sc[nt][3];
        }
        rs0 += __shfl_xor_sync(0xffffffffu, rs0, 1);
        rs0 += __shfl_xor_sync(0xffffffffu, rs0, 2);
        rs1 += __shfl_xor_sync(0xffffffffu, rs1, 1);
        rs1 += __shfl_xor_sync(0xffffffffu, rs1, 2);
        l_i[0] = l_i[0] * alpha0 + rs0;
        l_i[1] = l_i[1] * alpha1 + rs1;
#pragma unroll
        for (int nt = 0; nt < 16; nt++) {
            oa[nt][0] *= alpha0;
            oa[nt][1] *= alpha0;
            oa[nt][2] *= alpha1;
            oa[nt][3] *= alpha1;
        }

        // ---- O += P @ V (3-term: Ph*Vh + Pl*Vh + Ph*Vl); P frags from regs
#pragma unroll
        for (int kc = 0; kc < 4; kc++) {
            uint32_t ph[4], pl[4];
            split2(sc[2 * kc][0], sc[2 * kc][1], ph[0], pl[0]);
            split2(sc[2 * kc][2], sc[2 * kc][3], ph[1], pl[1]);
            split2(sc[2 * kc + 1][0], sc[2 * kc + 1][1], ph[2], pl[2]);
            split2(sc[2 * kc + 1][2], sc[2 * kc + 1][3], ph[3], pl[3]);
            const uint32_t vbase =
                (uint32_t)((kc * 16 + (lane & 15)) * ASTRIDE +
                           (((lane >> 4) << 3)) * 2);
#pragma unroll
            for (int dg = 0; dg < 8; dg++) {
                const uint32_t voff = vbase + (uint32_t)(dg * 32);
                uint32_t vh4[4], vl4[4];
                ldsm4t(vh4, Vh + voff);
                ldsm4t(vl4, Vl + voff);
                mma16816(oa[2 * dg], ph, vh4[0], vh4[1]);
                mma16816(oa[2 * dg], pl, vh4[0], vh4[1]);
                mma16816(oa[2 * dg], ph, vl4[0], vl4[1]);
                mma16816(oa[2 * dg + 1], ph, vh4[2], vh4[3]);
                mma16816(oa[2 * dg + 1], pl, vh4[2], vh4[3]);
                mma16816(oa[2 * dg + 1], ph, vl4[2], vl4[3]);
            }
        }
    }

    // ---- epilogue
    const float inv0 = 1.0f / l_i[0];
    const float inv1 = 1.0f / l_i[1];
    const int row0 = q0 + wr + (lane >> 2);
#pragma unroll
    for (int nt = 0; nt < 16; nt++) {
        const int d = nt * 8 + (lane & 3) * 2;
        float* p0 = &og[((size_t)(b * S_ + row0) * NH_ + h) * HD_ + d];
        float* p1 = &og[((size_t)(b * S_ + row0 + 8) * NH_ + h) * HD_ + d];
        *(float2*)p0 = make_float2(oa[nt][0] * inv0, oa[nt][1] * inv0);
        *(float2*)p1 = make_float2(oa[nt][2] * inv1, oa[nt][3] * inv1);
    }
}

// ============================================================================
// launch
// ============================================================================
extern "C" void kernel_launch(void* const* d_in, const int* in_sizes, int n_in,
                              void* d_out, int out_size) {
    const float* hidden = (const float*)d_in[0];
    const int*   pos    = (const int*)d_in[1];
    const float* Wq     = (const float*)d_in[2];
    const float* Wk     = (const float*)d_in[3];
    const float* Wv     = (const float*)d_in[4];
    const float* Wo     = (const float*)d_in[5];
    const float* qw     = (const float*)d_in[6];
    const float* kw     = (const float*)d_in[7];
    float* out = (float*)d_out;

    float *q, *k, *v, *attn, *ct, *st;
    cudaGetSymbolAddress((void**)&q,    g_q);
    cudaGetSymbolAddress((void**)&k,    g_k);
    cudaGetSymbolAddress((void**)&v,    g_v);
    cudaGetSymbolAddress((void**)&attn, g_attn);
    cudaGetSymbolAddress((void**)&ct,   g_cos);
    cudaGetSymbolAddress((void**)&st,   g_sin);

    const int gemm_smem = 2 * 40960;  // 80 KB
    cudaFuncSetAttribute(mma_gemm_kernel,
                         cudaFuncAttributeMaxDynamicSharedMemorySize, gemm_smem);

    // QKV projections (mma.sync bf16 x3)
    mma_gemm_kernel<<<dim3(2048 / 128, MROWS / 128), 256, gemm_smem>>>(
        hidden, Wq, q, MROWS, 2048, 1024);
    mma_gemm_kernel<<<dim3(1024 / 128, MROWS / 128), 256, gemm_smem>>>(
        hidden, Wk, k, MROWS, 1024, 1024);
    mma_gemm_kernel<<<dim3(1024 / 128, MROWS / 128), 256, gemm_smem>>>(
        hidden, Wv, v, MROWS, 1024, 1024);

    // RoPE table + RMSNorm/RoPE
    rope_table_kernel<<<(S_ * 64 + 255) / 256, 256>>>(pos, ct, st);
    {
        int total_warps = B_ * S_ * (NH_ + NKV_);
        norm_rope_kernel<<<total_warps / 8, 256>>>(q, k, qw, kw, ct, st);
    }

    // attention (mma.sync bf16 x3, fast exp2)
    {
        const int attn_smem = 139264;
        cudaFuncSetAttribute(attn_mma_kernel,
                             cudaFuncAttributeMaxDynamicSharedMemorySize,
                             attn_smem);
        attn_mma_kernel<<<dim3(S_ / 128, B_ * NH_), 256, attn_smem>>>(
            q, k, v, attn);
    }

    // output projection (mma.sync bf16 x3)
    mma_gemm_kernel<<<dim3(1024 / 128, MROWS / 128), 256, gemm_smem>>>(
        attn, Wo, out, MROWS, 1024, 2048);
}

// round 6
// speedup vs baseline: 2.5483x; 1.0489x over previous
#include <cuda_runtime.h>
#include <cuda_bf16.h>
#include <math.h>
#include <stdint.h>

#define B_   2
#define S_   2048
#define NH_  16
#define NKV_ 8
#define HD_  128
#define MROWS (B_ * S_)          // 4096

// ---------------- scratch (device globals; no allocation allowed) ----------
__device__ float g_q[(size_t)B_ * S_ * NH_ * HD_];
__device__ float g_k[(size_t)B_ * S_ * NKV_ * HD_];
__device__ float g_v[(size_t)B_ * S_ * NKV_ * HD_];
__device__ float g_attn[(size_t)B_ * S_ * NH_ * HD_];
__device__ float g_cos[S_ * 64];
__device__ float g_sin[S_ * 64];
// pre-split bf16 hi/lo copies
__device__ __nv_bfloat16 g_hid_h[(size_t)MROWS * 1024];
__device__ __nv_bfloat16 g_hid_l[(size_t)MROWS * 1024];
__device__ __nv_bfloat16 g_wq_h[(size_t)1024 * 2048];
__device__ __nv_bfloat16 g_wq_l[(size_t)1024 * 2048];
__device__ __nv_bfloat16 g_wk_h[(size_t)1024 * 1024];
__device__ __nv_bfloat16 g_wk_l[(size_t)1024 * 1024];
__device__ __nv_bfloat16 g_wv_h[(size_t)1024 * 1024];
__device__ __nv_bfloat16 g_wv_l[(size_t)1024 * 1024];
__device__ __nv_bfloat16 g_wo_h[(size_t)2048 * 1024];
__device__ __nv_bfloat16 g_wo_l[(size_t)2048 * 1024];
__device__ __nv_bfloat16 g_at_h[(size_t)MROWS * 2048];
__device__ __nv_bfloat16 g_at_l[(size_t)MROWS * 2048];

// ---------------- helpers ---------------------------------------------------
__device__ __forceinline__ uint32_t smem_u32(const void* p) {
    uint32_t a;
    asm("{ .reg .u64 t; cvta.to.shared.u64 t, %1; cvt.u32.u64 %0, t; }"
        : "=r"(a) : "l"(p));
    return a;
}
__device__ __forceinline__ void ldsm4(uint32_t* r, uint32_t addr) {
    asm volatile("ldmatrix.sync.aligned.m8n8.x4.shared.b16 {%0,%1,%2,%3}, [%4];"
                 : "=r"(r[0]), "=r"(r[1]), "=r"(r[2]), "=r"(r[3]) : "r"(addr));
}
__device__ __forceinline__ void ldsm4t(uint32_t* r, uint32_t addr) {
    asm volatile("ldmatrix.sync.aligned.m8n8.x4.trans.shared.b16 {%0,%1,%2,%3}, [%4];"
                 : "=r"(r[0]), "=r"(r[1]), "=r"(r[2]), "=r"(r[3]) : "r"(addr));
}
__device__ __forceinline__ void mma16816(float* c, const uint32_t* a,
                                         uint32_t b0, uint32_t b1) {
    asm volatile(
        "mma.sync.aligned.m16n8k16.row.col.f32.bf16.bf16.f32 "
        "{%0,%1,%2,%3}, {%4,%5,%6,%7}, {%8,%9}, {%0,%1,%2,%3};"
        : "+f"(c[0]), "+f"(c[1]), "+f"(c[2]), "+f"(c[3])
        : "r"(a[0]), "r"(a[1]), "r"(a[2]), "r"(a[3]), "r"(b0), "r"(b1));
}
__device__ __forceinline__ void sts128(uint32_t addr, uint32_t a, uint32_t b,
                                       uint32_t c, uint32_t d) {
    asm volatile("st.shared.v4.b32 [%0], {%1, %2, %3, %4};"
                 :: "r"(addr), "r"(a), "r"(b), "r"(c), "r"(d));
}
__device__ __forceinline__ void split2(float a, float b, uint32_t& hi, uint32_t& lo) {
    asm("cvt.rn.bf16x2.f32 %0, %1, %2;" : "=r"(hi) : "f"(b), "f"(a));
    float ha = __uint_as_float(hi << 16);
    float hb = __uint_as_float(hi & 0xffff0000u);
    float la = a - ha;
    float lb = b - hb;
    asm("cvt.rn.bf16x2.f32 %0, %1, %2;" : "=r"(lo) : "f"(lb), "f"(la));
}
// fast 2^y on the FMA pipe (no MUFU)
__device__ __forceinline__ float exp2fast(float y) {
    y = fmaxf(y, -126.0f);
    float r = y + 12582912.0f;
    float kf = r - 12582912.0f;
    float f = y - kf;
    float p = 1.3333558146e-3f;
    p = fmaf(p, f, 9.6181291076e-3f);
    p = fmaf(p, f, 5.5504108664e-2f);
    p = fmaf(p, f, 2.4022650696e-1f);
    p = fmaf(p, f, 6.9314718056e-1f);
    p = fmaf(p, f, 1.0f);
    return __int_as_float(__float_as_int(p) + (__float_as_int(r) << 23));
}

#define CP_ASYNC16(dst, src) \
    asm volatile("cp.async.cg.shared.global [%0], [%1], 16;" \
                 :: "r"(dst), "l"(src))
#define CP_COMMIT() asm volatile("cp.async.commit_group;" ::: "memory")
#define CP_WAIT1()  asm volatile("cp.async.wait_group 1;" ::: "memory")

// ============================================================================
// split: fp32 -> bf16 hi + bf16 lo (elementwise; count % 8 == 0)
// ============================================================================
__global__ void split_kernel(const float* __restrict__ in,
                             __nv_bfloat16* __restrict__ hi,
                             __nv_bfloat16* __restrict__ lo, int n8) {
    int idx = blockIdx.x * blockDim.x + threadIdx.x;
    if (idx >= n8) return;
    const float4 x0 = ((const float4*)in)[2 * idx];
    const float4 x1 = ((const float4*)in)[2 * idx + 1];
    uint4 h, l;
    split2(x0.x, x0.y, h.x, l.x);
    split2(x0.z, x0.w, h.y, l.y);
    split2(x1.x, x1.y, h.z, l.z);
    split2(x1.z, x1.w, h.w, l.w);
    ((uint4*)hi)[idx] = h;
    ((uint4*)lo)[idx] = l;
}

// ============================================================================
// GEMM v2: C[M,N] = A[M,K] @ B[K,N], inputs pre-split bf16 hi/lo.
// 3-term: Ah*Bh + Al*Bh + Ah*Bl. CTA tile 128x128, KC=32, cp.async 3 stages,
// 256 threads (8 warps, warp tile 64x32), 2 CTAs/SM.
// Stage layout: Ah@0 (128x80B) Al@10240 | Bh@20480 (32x272B) Bl@29184.
// Stage size 37888 B, 3 stages = 113664 B.
// ============================================================================
#define STG_SZ 37888u

__global__ __launch_bounds__(256, 2)
void mma_gemm2_kernel(const __nv_bfloat16* __restrict__ Ah,
                      const __nv_bfloat16* __restrict__ Al,
                      const __nv_bfloat16* __restrict__ Bh,
                      const __nv_bfloat16* __restrict__ Bl,
                      float* __restrict__ C, int M, int N, int K) {
    extern __shared__ __align__(16) char dsm[];
    const uint32_t sbase = smem_u32(dsm);

    const int tid  = threadIdx.x;
    const int lane = tid & 31;
    const int wid  = tid >> 5;
    const int m0 = blockIdx.y * 128;
    const int n0 = blockIdx.x * 128;
    const int wm = (wid >> 2) * 64;
    const int wn = (wid & 3) * 32;

    float acc[4][4][4];
#pragma unroll
    for (int i = 0; i < 4; i++)
#pragma unroll
        for (int j = 0; j < 4; j++)
#pragma unroll
            for (int r = 0; r < 4; r++) acc[i][j][r] = 0.0f;

    // loader indices
    const int a_row = tid >> 1;
    const int a_off = (tid & 1) * 16;     // elements (16 bf16 = 32 B)
    const int b_kr  = tid >> 3;
    const int b_off = (tid & 7) * 16;     // elements

    const int nch = K >> 5;               // K / 32

    // prologue: load chunks 0,1
#pragma unroll
    for (int c = 0; c < 2; c++) {
        const uint32_t st = sbase + (uint32_t)c * STG_SZ;
        const __nv_bfloat16* ah = Ah + (size_t)(m0 + a_row) * K + c * 32 + a_off;
        const __nv_bfloat16* al = Al + (size_t)(m0 + a_row) * K + c * 32 + a_off;
        uint32_t da = st + (uint32_t)(a_row * 80 + a_off * 2);
        CP_ASYNC16(da, ah);
        CP_ASYNC16(da + 16, ah + 8);
        CP_ASYNC16(da + 10240, al);
        CP_ASYNC16(da + 10256, al + 8);
        const __nv_bfloat16* bh = Bh + (size_t)(c * 32 + b_kr) * N + n0 + b_off;
        const __nv_bfloat16* bl = Bl + (size_t)(c * 32 + b_kr) * N + n0 + b_off;
        uint32_t db = st + 20480u + (uint32_t)(b_kr * 272 + b_off * 2);
        CP_ASYNC16(db, bh);
        CP_ASYNC16(db + 16, bh + 8);
        CP_ASYNC16(db + 8704, bl);
        CP_ASYNC16(db + 8720, bl + 8);
        CP_COMMIT();
    }

    for (int c = 0; c < nch; c++) {
        CP_WAIT1();
        __syncthreads();

        const uint32_t st = sbase + (uint32_t)(c % 3) * STG_SZ;
#pragma unroll
        for (int ks = 0; ks < 2; ks++) {
            uint32_t ah[4][4], al[4][4], bh[2][4], bl[2][4];
            const uint32_t aoff =
                st + (uint32_t)((wm + (lane & 15)) * 80 +
                                (ks * 16 + ((lane >> 4) << 3)) * 2);
#pragma unroll
            for (int mt = 0; mt < 4; mt++) {
                ldsm4(ah[mt], aoff + mt * 16 * 80);
                ldsm4(al[mt], aoff + mt * 16 * 80 + 10240);
            }
            const uint32_t bbase =
                st + 20480u + (uint32_t)((ks * 16 + (lane & 15)) * 272 +
                                         (wn + ((lane >> 4) << 3)) * 2);
#pragma unroll
            for (int ng = 0; ng < 2; ng++) {
                ldsm4t(bh[ng], bbase + ng * 32);
                ldsm4t(bl[ng], bbase + ng * 32 + 8704);
            }
#pragma unroll
            for (int mt = 0; mt < 4; mt++)
#pragma unroll
                for (int nt = 0; nt < 4; nt++) {
                    const int ng = nt >> 1;
                    const int hf = (nt & 1) * 2;
                    mma16816(acc[mt][nt], ah[mt], bh[ng][hf], bh[ng][hf + 1]);
                    mma16816(acc[mt][nt], al[mt], bh[ng][hf], bh[ng][hf + 1]);
                    mma16816(acc[mt][nt], ah[mt], bl[ng][hf], bl[ng][hf + 1]);
                }
        }
        __syncthreads();

        const int nc = c + 2;
        if (nc < nch) {
            const uint32_t st2 = sbase + (uint32_t)(nc % 3) * STG_SZ;
            const __nv_bfloat16* ahp = Ah + (size_t)(m0 + a_row) * K + nc * 32 + a_off;
            const __nv_bfloat16* alp = Al + (size_t)(m0 + a_row) * K + nc * 32 + a_off;
            uint32_t da = st2 + (uint32_t)(a_row * 80 + a_off * 2);
            CP_ASYNC16(da, ahp);
            CP_ASYNC16(da + 16, ahp + 8);
            CP_ASYNC16(da + 10240, alp);
            CP_ASYNC16(da + 10256, alp + 8);
            const __nv_bfloat16* bhp = Bh + (size_t)(nc * 32 + b_kr) * N + n0 + b_off;
            const __nv_bfloat16* blp = Bl + (size_t)(nc * 32 + b_kr) * N + n0 + b_off;
            uint32_t db = st2 + 20480u + (uint32_t)(b_kr * 272 + b_off * 2);
            CP_ASYNC16(db, bhp);
            CP_ASYNC16(db + 16, bhp + 8);
            CP_ASYNC16(db + 8704, blp);
            CP_ASYNC16(db + 8720, blp + 8);
        }
        CP_COMMIT();   // always commit (keeps wait_group bookkeeping exact)
    }

#pragma unroll
    for (int mt = 0; mt < 4; mt++)
#pragma unroll
        for (int nt = 0; nt < 4; nt++) {
            int row = m0 + wm + mt * 16 + (lane >> 2);
            int col = n0 + wn + nt * 8 + (lane & 3) * 2;
            *(float2*)&C[(size_t)row * N + col] =
                make_float2(acc[mt][nt][0], acc[mt][nt][1]);
            *(float2*)&C[(size_t)(row + 8) * N + col] =
                make_float2(acc[mt][nt][2], acc[mt][nt][3]);
        }
}

// ============================================================================
// RoPE cos/sin table
// ============================================================================
__global__ void rope_table_kernel(const int* __restrict__ pos,
                                  float* __restrict__ ctab,
                                  float* __restrict__ stab) {
    int idx = blockIdx.x * blockDim.x + threadIdx.x;
    if (idx >= S_ * 64) return;
    int s  = idx >> 6;
    int fi = idx & 63;
    float inv = (float)exp(-13.815510557964274 * (double)fi / 64.0);
    float ang = (float)pos[s] * inv;
    float c, sn;
    sincosf(ang, &sn, &c);
    ctab[idx] = c;
    stab[idx] = sn;
}

// ============================================================================
// RMSNorm + RoPE in-place over g_q and g_k.
// ============================================================================
__global__ void norm_rope_kernel(float* __restrict__ q, float* __restrict__ k,
                                 const float* __restrict__ qw,
                                 const float* __restrict__ kw,
                                 const float* __restrict__ ctab,
                                 const float* __restrict__ stab) {
    const int warp = (blockIdx.x * blockDim.x + threadIdx.x) >> 5;
    const int lane = threadIdx.x & 31;
    const int QROWS = B_ * S_ * NH_;

    float* ptr;
    const float* w;
    int s;
    if (warp < QROWS) {
        ptr = q + (size_t)warp * HD_;
        w = qw;
        s = (warp / NH_) % S_;
    } else {
        int r = warp - QROWS;
        ptr = k + (size_t)r * HD_;
        w = kw;
        s = (r / NKV_) % S_;
    }

    float4 x = ((const float4*)ptr)[lane];
    float ss = x.x * x.x + x.y * x.y + x.z * x.z + x.w * x.w;
#pragma unroll
    for (int off = 16; off; off >>= 1)
        ss += __shfl_xor_sync(0xffffffffu, ss, off);
    float rms = rsqrtf(ss * (1.0f / 128.0f) + 1e-6f);

    const int d0 = lane * 4;
    float xn[4];
    xn[0] = x.x * rms * w[d0 + 0];
    xn[1] = x.y * rms * w[d0 + 1];
    xn[2] = x.z * rms * w[d0 + 2];
    xn[3] = x.w * rms * w[d0 + 3];

    float out[4];
#pragma unroll
    for (int j = 0; j < 4; j++) {
        int fi = (d0 + j) & 63;
        float c  = ctab[s * 64 + fi];
        float sn = stab[s * 64 + fi];
        float partner = __shfl_xor_sync(0xffffffffu, xn[j], 16);
        out[j] = (lane < 16) ? (xn[j] * c - partner * sn)
                             : (xn[j] * c + partner * sn);
    }
    ((float4*)ptr)[lane] = make_float4(out[0], out[1], out[2], out[3]);
}

// ============================================================================
// Flash attention (unchanged R5 — proven)
// ============================================================================
#define ASTRIDE 272

__global__ __launch_bounds__(256, 1)
void attn_mma_kernel(const float* __restrict__ qg, const float* __restrict__ kg,
                     const float* __restrict__ vg, float* __restrict__ og) {
    extern __shared__ __align__(16) char asmem[];
    const uint32_t sb = smem_u32(asmem);
    const uint32_t Qh = sb, Ql = sb + 34816u;
    const uint32_t Kh = sb + 69632u, Kl = sb + 87040u;
    const uint32_t Vh = sb + 104448u, Vl = sb + 121856u;

    const int tid = threadIdx.x;
    const int lane = tid & 31;
    const int wid = tid >> 5;
    const int bh = blockIdx.y;
    const int b  = bh >> 4;
    const int h  = bh & 15;
    const int hk = h >> 1;
    const int qt = gridDim.x - 1 - blockIdx.x;
    const int q0 = qt * 128;
    const int wr = wid * 16;
    const float qscale = 0.1275174985f;   // 1/sqrt(128) * log2(e)

    {
        const int r = tid >> 1;
        const int hf = (tid & 1) * 64;
        const float* qp = &qg[((size_t)(b * S_ + q0 + r) * NH_ + h) * HD_ + hf];
        const uint32_t off = (uint32_t)(r * ASTRIDE + hf * 2);
#pragma unroll
        for (int j = 0; j < 8; j++) {
            float4 x0 = ((const float4*)qp)[2 * j];
            float4 x1 = ((const float4*)qp)[2 * j + 1];
            uint32_t h0, h1, h2, h3, l0, l1, l2, l3;
            split2(x0.x * qscale, x0.y * qscale, h0, l0);
            split2(x0.z * qscale, x0.w * qscale, h1, l1);
            split2(x1.x * qscale, x1.y * qscale, h2, l2);
            split2(x1.z * qscale, x1.w * qscale, h3, l3);
            sts128(Qh + off + j * 16, h0, h1, h2, h3);
            sts128(Ql + off + j * 16, l0, l1, l2, l3);
        }
    }

    float oa[16][4];
    float m_i[2], l_i[2];
#pragma unroll
    for (int nt = 0; nt < 16; nt++)
#pragma unroll
        for (int r = 0; r < 4; r++) oa[nt][r] = 0.0f;
    m_i[0] = m_i[1] = -1e30f;
    l_i[0] = l_i[1] = 0.0f;

    const int nkt = 2 * (qt + 1);
    for (int kt = 0; kt < nkt; kt++) {
        const int k0 = kt * 64;
        __syncthreads();
        {
            const int r = tid >> 2;
            const int qd = (tid & 3) * 32;
            const size_t gro = ((size_t)(b * S_ + k0 + r) * NKV_ + hk) * HD_ + qd;
            const uint32_t off = (uint32_t)(r * ASTRIDE + qd * 2);
            const float* kp = &kg[gro];
            const float* vp = &vg[gro];
#pragma unroll
            for (int j = 0; j < 4; j++) {
                float4 x0 = ((const float4*)kp)[2 * j];
                float4 x1 = ((const float4*)kp)[2 * j + 1];
                uint32_t h0, h1, h2, h3, l0, l1, l2, l3;
                split2(x0.x, x0.y, h0, l0);
                split2(x0.z, x0.w, h1, l1);
                split2(x1.x, x1.y, h2, l2);
                split2(x1.z, x1.w, h3, l3);
                sts128(Kh + off + j * 16, h0, h1, h2, h3);
                sts128(Kl + off + j * 16, l0, l1, l2, l3);
            }
#pragma unroll
            for (int j = 0; j < 4; j++) {
                float4 x0 = ((const float4*)vp)[2 * j];
                float4 x1 = ((const float4*)vp)[2 * j + 1];
                uint32_t h0, h1, h2, h3, l0, l1, l2, l3;
                split2(x0.x, x0.y, h0, l0);
                split2(x0.z, x0.w, h1, l1);
                split2(x1.x, x1.y, h2, l2);
                split2(x1.z, x1.w, h3, l3);
                sts128(Vh + off + j * 16, h0, h1, h2, h3);
                sts128(Vl + off + j * 16, l0, l1, l2, l3);
            }
        }
        __syncthreads();

        float sc[8][4];
#pragma unroll
        for (int nt = 0; nt < 8; nt++)
#pragma unroll
            for (int r = 0; r < 4; r++) sc[nt][r] = 0.0f;

#pragma unroll
        for (int kc = 0; kc < 8; kc++) {
            const uint32_t aoff =
                (uint32_t)((wr + (lane & 15)) * ASTRIDE +
                           (kc * 16 + ((lane >> 4) << 3)) * 2);
            uint32_t ah[4], al[4];
            ldsm4(ah, Qh + aoff);
            ldsm4(al, Ql + aoff);
            const uint32_t bbase =
                (uint32_t)((((lane >> 4) << 3) + (lane & 7)) * ASTRIDE +
                           (kc * 16 + ((lane >> 3) & 1) * 8) * 2);
#pragma unroll
            for (int bg = 0; bg < 4; bg++) {
                const uint32_t boff = bbase + (uint32_t)(bg * 16 * ASTRIDE);
                uint32_t bh4[4], bl4[4];
                ldsm4(bh4, Kh + boff);
                ldsm4(bl4, Kl + boff);
                mma16816(sc[2 * bg], ah, bh4[0], bh4[1]);
                mma16816(sc[2 * bg], al, bh4[0], bh4[1]);
                mma16816(sc[2 * bg], ah, bl4[0], bl4[1]);
                mma16816(sc[2 * bg + 1], ah, bh4[2], bh4[3]);
                mma16816(sc[2 * bg + 1], al, bh4[2], bh4[3]);
                mma16816(sc[2 * bg + 1], ah, bl4[2], bl4[3]);
            }
        }

        const int row0 = q0 + wr + (lane >> 2);
        const int row1 = row0 + 8;
        if (kt >= 2 * qt) {
#pragma unroll
            for (int nt = 0; nt < 8; nt++) {
                int cb = k0 + nt * 8 + (lane & 3) * 2;
                if (cb > row0) sc[nt][0] = -1e30f;
                if (cb + 1 > row0) sc[nt][1] = -1e30f;
                if (cb > row1) sc[nt][2] = -1e30f;
                if (cb + 1 > row1) sc[nt][3] = -1e30f;
            }
        }

        float mx0 = sc[0][0], mx1 = sc[0][2];
#pragma unroll
        for (int nt = 0; nt < 8; nt++) {
            mx0 = fmaxf(mx0, fmaxf(sc[nt][0], sc[nt][1]));
            mx1 = fmaxf(mx1, fmaxf(sc[nt][2], sc[nt][3]));
        }
        mx0 = fmaxf(mx0, __shfl_xor_sync(0xffffffffu, mx0, 1));
        mx0 = fmaxf(mx0, __shfl_xor_sync(0xffffffffu, mx0, 2));
        mx1 = fmaxf(mx1, __shfl_xor_sync(0xffffffffu, mx1, 1));
        mx1 = fmaxf(mx1, __shfl_xor_sync(0xffffffffu, mx1, 2));
        const float mn0 = fmaxf(m_i[0], mx0);
        const float mn1 = fmaxf(m_i[1], mx1);
        const float alpha0 = exp2fast(m_i[0] - mn0);
        const float alpha1 = exp2fast(m_i[1] - mn1);
        m_i[0] = mn0;
        m_i[1] = mn1;

        float rs0 = 0.0f, rs1 = 0.0f;
#pragma unroll
        for (int nt = 0; nt < 8; nt++) {
            sc[nt][0] = exp2fast(sc[nt][0] - mn0);
            sc[nt][1] = exp2fast(sc[nt][1] - mn0);
            sc[nt][2] = exp2fast(sc[nt][2] - mn1);
            sc[nt][3] = exp2fast(sc[nt][3] - mn1);
            rs0 += sc[nt][0] + sc[nt][1];
            rs1 += sc[nt][2] + sc[nt][3];
        }
        rs0 += __shfl_xor_sync(0xffffffffu, rs0, 1);
        rs0 += __shfl_xor_sync(0xffffffffu, rs0, 2);
        rs1 += __shfl_xor_sync(0xffffffffu, rs1, 1);
        rs1 += __shfl_xor_sync(0xffffffffu, rs1, 2);
        l_i[0] = l_i[0] * alpha0 + rs0;
        l_i[1] = l_i[1] * alpha1 + rs1;
#pragma unroll
        for (int nt = 0; nt < 16; nt++) {
            oa[nt][0] *= alpha0;
            oa[nt][1] *= alpha0;
            oa[nt][2] *= alpha1;
            oa[nt][3] *= alpha1;
        }

#pragma unroll
        for (int kc = 0; kc < 4; kc++) {
            uint32_t ph[4], pl[4];
            split2(sc[2 * kc][0], sc[2 * kc][1], ph[0], pl[0]);
            split2(sc[2 * kc][2], sc[2 * kc][3], ph[1], pl[1]);
            split2(sc[2 * kc + 1][0], sc[2 * kc + 1][1], ph[2], pl[2]);
            split2(sc[2 * kc + 1][2], sc[2 * kc + 1][3], ph[3], pl[3]);
            const uint32_t vbase =
                (uint32_t)((kc * 16 + (lane & 15)) * ASTRIDE +
                           (((lane >> 4) << 3)) * 2);
#pragma unroll
            for (int dg = 0; dg < 8; dg++) {
                const uint32_t voff = vbase + (uint32_t)(dg * 32);
                uint32_t vh4[4], vl4[4];
                ldsm4t(vh4, Vh + voff);
                ldsm4t(vl4, Vl + voff);
                mma16816(oa[2 * dg], ph, vh4[0], vh4[1]);
                mma16816(oa[2 * dg], pl, vh4[0], vh4[1]);
                mma16816(oa[2 * dg], ph, vl4[0], vl4[1]);
                mma16816(oa[2 * dg + 1], ph, vh4[2], vh4[3]);
                mma16816(oa[2 * dg + 1], pl, vh4[2], vh4[3]);
                mma16816(oa[2 * dg + 1], ph, vl4[2], vl4[3]);
            }
        }
    }

    const float inv0 = 1.0f / l_i[0];
    const float inv1 = 1.0f / l_i[1];
    const int row0 = q0 + wr + (lane >> 2);
#pragma unroll
    for (int nt = 0; nt < 16; nt++) {
        const int d = nt * 8 + (lane & 3) * 2;
        float* p0 = &og[((size_t)(b * S_ + row0) * NH_ + h) * HD_ + d];
        float* p1 = &og[((size_t)(b * S_ + row0 + 8) * NH_ + h) * HD_ + d];
        *(float2*)p0 = make_float2(oa[nt][0] * inv0, oa[nt][1] * inv0);
        *(float2*)p1 = make_float2(oa[nt][2] * inv1, oa[nt][3] * inv1);
    }
}

// ============================================================================
// launch
// ============================================================================
extern "C" void kernel_launch(void* const* d_in, const int* in_sizes, int n_in,
                              void* d_out, int out_size) {
    const float* hidden = (const float*)d_in[0];
    const int*   pos    = (const int*)d_in[1];
    const float* Wq     = (const float*)d_in[2];
    const float* Wk     = (const float*)d_in[3];
    const float* Wv     = (const float*)d_in[4];
    const float* Wo     = (const float*)d_in[5];
    const float* qw     = (const float*)d_in[6];
    const float* kw     = (const float*)d_in[7];
    float* out = (float*)d_out;

    float *q, *k, *v, *attn, *ct, *st;
    cudaGetSymbolAddress((void**)&q,    g_q);
    cudaGetSymbolAddress((void**)&k,    g_k);
    cudaGetSymbolAddress((void**)&v,    g_v);
    cudaGetSymbolAddress((void**)&attn, g_attn);
    cudaGetSymbolAddress((void**)&ct,   g_cos);
    cudaGetSymbolAddress((void**)&st,   g_sin);

    __nv_bfloat16 *hidh, *hidl, *wqh, *wql, *wkh, *wkl, *wvh, *wvl,
                  *woh, *wol, *ath, *atl;
    cudaGetSymbolAddress((void**)&hidh, g_hid_h);
    cudaGetSymbolAddress((void**)&hidl, g_hid_l);
    cudaGetSymbolAddress((void**)&wqh,  g_wq_h);
    cudaGetSymbolAddress((void**)&wql,  g_wq_l);
    cudaGetSymbolAddress((void**)&wkh,  g_wk_h);
    cudaGetSymbolAddress((void**)&wkl,  g_wk_l);
    cudaGetSymbolAddress((void**)&wvh,  g_wv_h);
    cudaGetSymbolAddress((void**)&wvl,  g_wv_l);
    cudaGetSymbolAddress((void**)&woh,  g_wo_h);
    cudaGetSymbolAddress((void**)&wol,  g_wo_l);
    cudaGetSymbolAddress((void**)&ath,  g_at_h);
    cudaGetSymbolAddress((void**)&atl,  g_at_l);

    // ---- pre-split inputs to bf16 hi/lo
    {
        int n8;
        n8 = MROWS * 1024 / 8;
        split_kernel<<<(n8 + 255) / 256, 256>>>(hidden, hidh, hidl, n8);
        n8 = 1024 * 2048 / 8;
        split_kernel<<<(n8 + 255) / 256, 256>>>(Wq, wqh, wql, n8);
        n8 = 1024 * 1024 / 8;
        split_kernel<<<(n8 + 255) / 256, 256>>>(Wk, wkh, wkl, n8);
        split_kernel<<<(n8 + 255) / 256, 256>>>(Wv, wvh, wvl, n8);
        n8 = 2048 * 1024 / 8;
        split_kernel<<<(n8 + 255) / 256, 256>>>(Wo, woh, wol, n8);
    }

    const int gemm_smem = 3 * (int)STG_SZ;   // 113664
    cudaFuncSetAttribute(mma_gemm2_kernel,
                         cudaFuncAttributeMaxDynamicSharedMemorySize, gemm_smem);

    // QKV projections
    mma_gemm2_kernel<<<dim3(2048 / 128, MROWS / 128), 256, gemm_smem>>>(
        hidh, hidl, wqh, wql, q, MROWS, 2048, 1024);
    mma_gemm2_kernel<<<dim3(1024 / 128, MROWS / 128), 256, gemm_smem>>>(
        hidh, hidl, wkh, wkl, k, MROWS, 1024, 1024);
    mma_gemm2_kernel<<<dim3(1024 / 128, MROWS / 128), 256, gemm_smem>>>(
        hidh, hidl, wvh, wvl, v, MROWS, 1024, 1024);

    // RoPE table + RMSNorm/RoPE
    rope_table_kernel<<<(S_ * 64 + 255) / 256, 256>>>(pos, ct, st);
    {
        int total_warps = B_ * S_ * (NH_ + NKV_);
        norm_rope_kernel<<<total_warps / 8, 256>>>(q, k, qw, kw, ct, st);
    }

    // attention
    {
        const int attn_smem = 139264;
        cudaFuncSetAttribute(attn_mma_kernel,
                             cudaFuncAttributeMaxDynamicSharedMemorySize,
                             attn_smem);
        attn_mma_kernel<<<dim3(S_ / 128, B_ * NH_), 256, attn_smem>>>(
            q, k, v, attn);
    }

    // split attention output, then output projection
    {
        int n8 = MROWS * 2048 / 8;
        split_kernel<<<(n8 + 255) / 256, 256>>>(attn, ath, atl, n8);
    }
    mma_gemm2_kernel<<<dim3(1024 / 128, MROWS / 128), 256, gemm_smem>>>(
        ath, atl, woh, wol, out, MROWS, 1024, 2048);
}

// round 7
// speedup vs baseline: 2.8942x; 1.1357x over previous
#include <cuda_runtime.h>
#include <cuda_bf16.h>
#include <cuda_fp16.h>
#include <math.h>
#include <stdint.h>

#define B_   2
#define S_   2048
#define NH_  16
#define NKV_ 8
#define HD_  128
#define MROWS (B_ * S_)          // 4096

// ---------------- scratch (device globals; no allocation allowed) ----------
__device__ float g_q[(size_t)B_ * S_ * NH_ * HD_];
__device__ float g_k[(size_t)B_ * S_ * NKV_ * HD_];
__device__ float g_v[(size_t)B_ * S_ * NKV_ * HD_];
__device__ float g_attn[(size_t)B_ * S_ * NH_ * HD_];
__device__ float g_cos[S_ * 64];
__device__ float g_sin[S_ * 64];
// pre-split fp16 copies (A-side: hi+lo; B-side: hi only)
__device__ __half g_hid_h[(size_t)MROWS * 1024];
__device__ __half g_hid_l[(size_t)MROWS * 1024];
__device__ __half g_wq_h[(size_t)1024 * 2048];
__device__ __half g_wk_h[(size_t)1024 * 1024];
__device__ __half g_wv_h[(size_t)1024 * 1024];
__device__ __half g_wo_h[(size_t)2048 * 1024];
__device__ __half g_at_h[(size_t)MROWS * 2048];
__device__ __half g_at_l[(size_t)MROWS * 2048];

// ---------------- helpers ---------------------------------------------------
__device__ __forceinline__ uint32_t smem_u32(const void* p) {
    uint32_t a;
    asm("{ .reg .u64 t; cvta.to.shared.u64 t, %1; cvt.u32.u64 %0, t; }"
        : "=r"(a) : "l"(p));
    return a;
}
__device__ __forceinline__ void ldsm4(uint32_t* r, uint32_t addr) {
    asm volatile("ldmatrix.sync.aligned.m8n8.x4.shared.b16 {%0,%1,%2,%3}, [%4];"
                 : "=r"(r[0]), "=r"(r[1]), "=r"(r[2]), "=r"(r[3]) : "r"(addr));
}
__device__ __forceinline__ void ldsm4t(uint32_t* r, uint32_t addr) {
    asm volatile("ldmatrix.sync.aligned.m8n8.x4.trans.shared.b16 {%0,%1,%2,%3}, [%4];"
                 : "=r"(r[0]), "=r"(r[1]), "=r"(r[2]), "=r"(r[3]) : "r"(addr));
}
// bf16 mma (attention)
__device__ __forceinline__ void mma16816(float* c, const uint32_t* a,
                                         uint32_t b0, uint32_t b1) {
    asm volatile(
        "mma.sync.aligned.m16n8k16.row.col.f32.bf16.bf16.f32 "
        "{%0,%1,%2,%3}, {%4,%5,%6,%7}, {%8,%9}, {%0,%1,%2,%3};"
        : "+f"(c[0]), "+f"(c[1]), "+f"(c[2]), "+f"(c[3])
        : "r"(a[0]), "r"(a[1]), "r"(a[2]), "r"(a[3]), "r"(b0), "r"(b1));
}
// fp16 mma, f32 accum (GEMMs)
__device__ __forceinline__ void mma16816h(float* c, const uint32_t* a,
                                          uint32_t b0, uint32_t b1) {
    asm volatile(
        "mma.sync.aligned.m16n8k16.row.col.f32.f16.f16.f32 "
        "{%0,%1,%2,%3}, {%4,%5,%6,%7}, {%8,%9}, {%0,%1,%2,%3};"
        : "+f"(c[0]), "+f"(c[1]), "+f"(c[2]), "+f"(c[3])
        : "r"(a[0]), "r"(a[1]), "r"(a[2]), "r"(a[3]), "r"(b0), "r"(b1));
}
__device__ __forceinline__ void sts128(uint32_t addr, uint32_t a, uint32_t b,
                                       uint32_t c, uint32_t d) {
    asm volatile("st.shared.v4.b32 [%0], {%1, %2, %3, %4};"
                 :: "r"(addr), "r"(a), "r"(b), "r"(c), "r"(d));
}
// bf16 hi/lo split (attention)
__device__ __forceinline__ void split2(float a, float b, uint32_t& hi, uint32_t& lo) {
    asm("cvt.rn.bf16x2.f32 %0, %1, %2;" : "=r"(hi) : "f"(b), "f"(a));
    float ha = __uint_as_float(hi << 16);
    float hb = __uint_as_float(hi & 0xffff0000u);
    float la = a - ha;
    float lb = b - hb;
    asm("cvt.rn.bf16x2.f32 %0, %1, %2;" : "=r"(lo) : "f"(lb), "f"(la));
}
// fp16 hi/lo split
__device__ __forceinline__ void split2h(float a, float b, uint32_t& hi, uint32_t& lo) {
    __half2 h = __floats2half2_rn(a, b);
    float2 hf = __half22float2(h);
    __half2 l = __floats2half2_rn(a - hf.x, b - hf.y);
    hi = *(uint32_t*)&h;
    lo = *(uint32_t*)&l;
}
// fast 2^y on the FMA pipe (no MUFU)
__device__ __forceinline__ float exp2fast(float y) {
    y = fmaxf(y, -126.0f);
    float r = y + 12582912.0f;
    float kf = r - 12582912.0f;
    float f = y - kf;
    float p = 1.3333558146e-3f;
    p = fmaf(p, f, 9.6181291076e-3f);
    p = fmaf(p, f, 5.5504108664e-2f);
    p = fmaf(p, f, 2.4022650696e-1f);
    p = fmaf(p, f, 6.9314718056e-1f);
    p = fmaf(p, f, 1.0f);
    return __int_as_float(__float_as_int(p) + (__float_as_int(r) << 23));
}

#define CP_ASYNC16(dst, src) \
    asm volatile("cp.async.cg.shared.global [%0], [%1], 16;" \
                 :: "r"(dst), "l"(src))
#define CP_COMMIT() asm volatile("cp.async.commit_group;" ::: "memory")
#define CP_WAIT1()  asm volatile("cp.async.wait_group 1;" ::: "memory")

// ============================================================================
// split kernels: fp32 -> fp16 hi (+ lo)
// ============================================================================
__global__ void split_hl_kernel(const float* __restrict__ in,
                                __half* __restrict__ hi,
                                __half* __restrict__ lo, int n8) {
    int idx = blockIdx.x * blockDim.x + threadIdx.x;
    if (idx >= n8) return;
    const float4 x0 = ((const float4*)in)[2 * idx];
    const float4 x1 = ((const float4*)in)[2 * idx + 1];
    uint4 h, l;
    split2h(x0.x, x0.y, h.x, l.x);
    split2h(x0.z, x0.w, h.y, l.y);
    split2h(x1.x, x1.y, h.z, l.z);
    split2h(x1.z, x1.w, h.w, l.w);
    ((uint4*)hi)[idx] = h;
    ((uint4*)lo)[idx] = l;
}

__global__ void split_h_kernel(const float* __restrict__ in,
                               __half* __restrict__ hi, int n8) {
    int idx = blockIdx.x * blockDim.x + threadIdx.x;
    if (idx >= n8) return;
    const float4 x0 = ((const float4*)in)[2 * idx];
    const float4 x1 = ((const float4*)in)[2 * idx + 1];
    uint4 h;
    __half2 t;
    t = __floats2half2_rn(x0.x, x0.y); h.x = *(uint32_t*)&t;
    t = __floats2half2_rn(x0.z, x0.w); h.y = *(uint32_t*)&t;
    t = __floats2half2_rn(x1.x, x1.y); h.z = *(uint32_t*)&t;
    t = __floats2half2_rn(x1.z, x1.w); h.w = *(uint32_t*)&t;
    ((uint4*)hi)[idx] = h;
}

// ============================================================================
// GEMM v3: C[M,N] = A[M,K] @ B[K,N], fp16 2-term: Ah*Bh + Al*Bh.
// A pre-split fp16 hi/lo; B pre-converted fp16 hi only.
// CTA tile 128x128, KC=32, cp.async 3 stages, 256 threads, 2 CTAs/SM.
// Stage: Ah@0 (128x80B) Al@10240 | Bh@20480 (32x272B). Stage = 29184 B.
// ============================================================================
#define STG_SZ 29184u

__global__ __launch_bounds__(256, 2)
void mma_gemm3_kernel(const __half* __restrict__ Ah,
                      const __half* __restrict__ Al,
                      const __half* __restrict__ Bh,
                      float* __restrict__ C, int M, int N, int K) {
    extern __shared__ __align__(16) char dsm[];
    const uint32_t sbase = smem_u32(dsm);

    const int tid  = threadIdx.x;
    const int lane = tid & 31;
    const int wid  = tid >> 5;
    const int m0 = blockIdx.y * 128;
    const int n0 = blockIdx.x * 128;
    const int wm = (wid >> 2) * 64;
    const int wn = (wid & 3) * 32;

    float acc[4][4][4];
#pragma unroll
    for (int i = 0; i < 4; i++)
#pragma unroll
        for (int j = 0; j < 4; j++)
#pragma unroll
            for (int r = 0; r < 4; r++) acc[i][j][r] = 0.0f;

    const int a_row = tid >> 1;
    const int a_off = (tid & 1) * 16;
    const int b_kr  = tid >> 3;
    const int b_off = (tid & 7) * 16;

    const int nch = K >> 5;

#pragma unroll
    for (int c = 0; c < 2; c++) {
        const uint32_t st = sbase + (uint32_t)c * STG_SZ;
        const __half* ah = Ah + (size_t)(m0 + a_row) * K + c * 32 + a_off;
        const __half* al = Al + (size_t)(m0 + a_row) * K + c * 32 + a_off;
        uint32_t da = st + (uint32_t)(a_row * 80 + a_off * 2);
        CP_ASYNC16(da, ah);
        CP_ASYNC16(da + 16, ah + 8);
        CP_ASYNC16(da + 10240, al);
        CP_ASYNC16(da + 10256, al + 8);
        const __half* bh = Bh + (size_t)(c * 32 + b_kr) * N + n0 + b_off;
        uint32_t db = st + 20480u + (uint32_t)(b_kr * 272 + b_off * 2);
        CP_ASYNC16(db, bh);
        CP_ASYNC16(db + 16, bh + 8);
        CP_COMMIT();
    }

    for (int c = 0; c < nch; c++) {
        CP_WAIT1();
        __syncthreads();

        const uint32_t st = sbase + (uint32_t)(c % 3) * STG_SZ;
#pragma unroll
        for (int ks = 0; ks < 2; ks++) {
            uint32_t ah[4][4], al[4][4], bh[2][4];
            const uint32_t aoff =
                st + (uint32_t)((wm + (lane & 15)) * 80 +
                                (ks * 16 + ((lane >> 4) << 3)) * 2);
#pragma unroll
            for (int mt = 0; mt < 4; mt++) {
                ldsm4(ah[mt], aoff + mt * 16 * 80);
                ldsm4(al[mt], aoff + mt * 16 * 80 + 10240);
            }
            const uint32_t bbase =
                st + 20480u + (uint32_t)((ks * 16 + (lane & 15)) * 272 +
                                         (wn + ((lane >> 4) << 3)) * 2);
#pragma unroll
            for (int ng = 0; ng < 2; ng++)
                ldsm4t(bh[ng], bbase + ng * 32);
#pragma unroll
            for (int mt = 0; mt < 4; mt++)
#pragma unroll
                for (int nt = 0; nt < 4; nt++) {
                    const int ng = nt >> 1;
                    const int hf = (nt & 1) * 2;
                    mma16816h(acc[mt][nt], ah[mt], bh[ng][hf], bh[ng][hf + 1]);
                    mma16816h(acc[mt][nt], al[mt], bh[ng][hf], bh[ng][hf + 1]);
                }
        }
        __syncthreads();

        const int nc = c + 2;
        if (nc < nch) {
            const uint32_t st2 = sbase + (uint32_t)(nc % 3) * STG_SZ;
            const __half* ahp = Ah + (size_t)(m0 + a_row) * K + nc * 32 + a_off;
            const __half* alp = Al + (size_t)(m0 + a_row) * K + nc * 32 + a_off;
            uint32_t da = st2 + (uint32_t)(a_row * 80 + a_off * 2);
            CP_ASYNC16(da, ahp);
            CP_ASYNC16(da + 16, ahp + 8);
            CP_ASYNC16(da + 10240, alp);
            CP_ASYNC16(da + 10256, alp + 8);
            const __half* bhp = Bh + (size_t)(nc * 32 + b_kr) * N + n0 + b_off;
            uint32_t db = st2 + 20480u + (uint32_t)(b_kr * 272 + b_off * 2);
            CP_ASYNC16(db, bhp);
            CP_ASYNC16(db + 16, bhp + 8);
        }
        CP_COMMIT();
    }

#pragma unroll
    for (int mt = 0; mt < 4; mt++)
#pragma unroll
        for (int nt = 0; nt < 4; nt++) {
            int row = m0 + wm + mt * 16 + (lane >> 2);
            int col = n0 + wn + nt * 8 + (lane & 3) * 2;
            *(float2*)&C[(size_t)row * N + col] =
                make_float2(acc[mt][nt][0], acc[mt][nt][1]);
            *(float2*)&C[(size_t)(row + 8) * N + col] =
                make_float2(acc[mt][nt][2], acc[mt][nt][3]);
        }
}

// ============================================================================
// RoPE cos/sin table
// ============================================================================
__global__ void rope_table_kernel(const int* __restrict__ pos,
                                  float* __restrict__ ctab,
                                  float* __restrict__ stab) {
    int idx = blockIdx.x * blockDim.x + threadIdx.x;
    if (idx >= S_ * 64) return;
    int s  = idx >> 6;
    int fi = idx & 63;
    float inv = (float)exp(-13.815510557964274 * (double)fi / 64.0);
    float ang = (float)pos[s] * inv;
    float c, sn;
    sincosf(ang, &sn, &c);
    ctab[idx] = c;
    stab[idx] = sn;
}

// ============================================================================
// RMSNorm + RoPE in-place over g_q and g_k.
// ============================================================================
__global__ void norm_rope_kernel(float* __restrict__ q, float* __restrict__ k,
                                 const float* __restrict__ qw,
                                 const float* __restrict__ kw,
                                 const float* __restrict__ ctab,
                                 const float* __restrict__ stab) {
    const int warp = (blockIdx.x * blockDim.x + threadIdx.x) >> 5;
    const int lane = threadIdx.x & 31;
    const int QROWS = B_ * S_ * NH_;

    float* ptr;
    const float* w;
    int s;
    if (warp < QROWS) {
        ptr = q + (size_t)warp * HD_;
        w = qw;
        s = (warp / NH_) % S_;
    } else {
        int r = warp - QROWS;
        ptr = k + (size_t)r * HD_;
        w = kw;
        s = (r / NKV_) % S_;
    }

    float4 x = ((const float4*)ptr)[lane];
    float ss = x.x * x.x + x.y * x.y + x.z * x.z + x.w * x.w;
#pragma unroll
    for (int off = 16; off; off >>= 1)
        ss += __shfl_xor_sync(0xffffffffu, ss, off);
    float rms = rsqrtf(ss * (1.0f / 128.0f) + 1e-6f);

    const int d0 = lane * 4;
    float xn[4];
    xn[0] = x.x * rms * w[d0 + 0];
    xn[1] = x.y * rms * w[d0 + 1];
    xn[2] = x.z * rms * w[d0 + 2];
    xn[3] = x.w * rms * w[d0 + 3];

    float out[4];
#pragma unroll
    for (int j = 0; j < 4; j++) {
        int fi = (d0 + j) & 63;
        float c  = ctab[s * 64 + fi];
        float sn = stab[s * 64 + fi];
        float partner = __shfl_xor_sync(0xffffffffu, xn[j], 16);
        out[j] = (lane < 16) ? (xn[j] * c - partner * sn)
                             : (xn[j] * c + partner * sn);
    }
    ((float4*)ptr)[lane] = make_float4(out[0], out[1], out[2], out[3]);
}

// ============================================================================
// Flash attention (unchanged R5/R6 — proven; bf16 3-term)
// ============================================================================
#define ASTRIDE 272

__global__ __launch_bounds__(256, 1)
void attn_mma_kernel(const float* __restrict__ qg, const float* __restrict__ kg,
                     const float* __restrict__ vg, float* __restrict__ og) {
    extern __shared__ __align__(16) char asmem[];
    const uint32_t sb = smem_u32(asmem);
    const uint32_t Qh = sb, Ql = sb + 34816u;
    const uint32_t Kh = sb + 69632u, Kl = sb + 87040u;
    const uint32_t Vh = sb + 104448u, Vl = sb + 121856u;

    const int tid = threadIdx.x;
    const int lane = tid & 31;
    const int wid = tid >> 5;
    const int bh = blockIdx.y;
    const int b  = bh >> 4;
    const int h  = bh & 15;
    const int hk = h >> 1;
    const int qt = gridDim.x - 1 - blockIdx.x;
    const int q0 = qt * 128;
    const int wr = wid * 16;
    const float qscale = 0.1275174985f;   // 1/sqrt(128) * log2(e)

    {
        const int r = tid >> 1;
        const int hf = (tid & 1) * 64;
        const float* qp = &qg[((size_t)(b * S_ + q0 + r) * NH_ + h) * HD_ + hf];
        const uint32_t off = (uint32_t)(r * ASTRIDE + hf * 2);
#pragma unroll
        for (int j = 0; j < 8; j++) {
            float4 x0 = ((const float4*)qp)[2 * j];
            float4 x1 = ((const float4*)qp)[2 * j + 1];
            uint32_t h0, h1, h2, h3, l0, l1, l2, l3;
            split2(x0.x * qscale, x0.y * qscale, h0, l0);
            split2(x0.z * qscale, x0.w * qscale, h1, l1);
            split2(x1.x * qscale, x1.y * qscale, h2, l2);
            split2(x1.z * qscale, x1.w * qscale, h3, l3);
            sts128(Qh + off + j * 16, h0, h1, h2, h3);
            sts128(Ql + off + j * 16, l0, l1, l2, l3);
        }
    }

    float oa[16][4];
    float m_i[2], l_i[2];
#pragma unroll
    for (int nt = 0; nt < 16; nt++)
#pragma unroll
        for (int r = 0; r < 4; r++) oa[nt][r] = 0.0f;
    m_i[0] = m_i[1] = -1e30f;
    l_i[0] = l_i[1] = 0.0f;

    const int nkt = 2 * (qt + 1);
    for (int kt = 0; kt < nkt; kt++) {
        const int k0 = kt * 64;
        __syncthreads();
        {
            const int r = tid >> 2;
            const int qd = (tid & 3) * 32;
            const size_t gro = ((size_t)(b * S_ + k0 + r) * NKV_ + hk) * HD_ + qd;
            const uint32_t off = (uint32_t)(r * ASTRIDE + qd * 2);
            const float* kp = &kg[gro];
            const float* vp = &vg[gro];
#pragma unroll
            for (int j = 0; j < 4; j++) {
                float4 x0 = ((const float4*)kp)[2 * j];
                float4 x1 = ((const float4*)kp)[2 * j + 1];
                uint32_t h0, h1, h2, h3, l0, l1, l2, l3;
                split2(x0.x, x0.y, h0, l0);
                split2(x0.z, x0.w, h1, l1);
                split2(x1.x, x1.y, h2, l2);
                split2(x1.z, x1.w, h3, l3);
                sts128(Kh + off + j * 16, h0, h1, h2, h3);
                sts128(Kl + off + j * 16, l0, l1, l2, l3);
            }
#pragma unroll
            for (int j = 0; j < 4; j++) {
                float4 x0 = ((const float4*)vp)[2 * j];
                float4 x1 = ((const float4*)vp)[2 * j + 1];
                uint32_t h0, h1, h2, h3, l0, l1, l2, l3;
                split2(x0.x, x0.y, h0, l0);
                split2(x0.z, x0.w, h1, l1);
                split2(x1.x, x1.y, h2, l2);
                split2(x1.z, x1.w, h3, l3);
                sts128(Vh + off + j * 16, h0, h1, h2, h3);
                sts128(Vl + off + j * 16, l0, l1, l2, l3);
            }
        }
        __syncthreads();

        float sc[8][4];
#pragma unroll
        for (int nt = 0; nt < 8; nt++)
#pragma unroll
            for (int r = 0; r < 4; r++) sc[nt][r] = 0.0f;

#pragma unroll
        for (int kc = 0; kc < 8; kc++) {
            const uint32_t aoff =
                (uint32_t)((wr + (lane & 15)) * ASTRIDE +
                           (kc * 16 + ((lane >> 4) << 3)) * 2);
            uint32_t ah[4], al[4];
            ldsm4(ah, Qh + aoff);
            ldsm4(al, Ql + aoff);
            const uint32_t bbase =
                (uint32_t)((((lane >> 4) << 3) + (lane & 7)) * ASTRIDE +
                           (kc * 16 + ((lane >> 3) & 1) * 8) * 2);
#pragma unroll
            for (int bg = 0; bg < 4; bg++) {
                const uint32_t boff = bbase + (uint32_t)(bg * 16 * ASTRIDE);
                uint32_t bh4[4], bl4[4];
                ldsm4(bh4, Kh + boff);
                ldsm4(bl4, Kl + boff);
                mma16816(sc[2 * bg], ah, bh4[0], bh4[1]);
                mma16816(sc[2 * bg], al, bh4[0], bh4[1]);
                mma16816(sc[2 * bg], ah, bl4[0], bl4[1]);
                mma16816(sc[2 * bg + 1], ah, bh4[2], bh4[3]);
                mma16816(sc[2 * bg + 1], al, bh4[2], bh4[3]);
                mma16816(sc[2 * bg + 1], ah, bl4[2], bl4[3]);
            }
        }

        const int row0 = q0 + wr + (lane >> 2);
        const int row1 = row0 + 8;
        if (kt >= 2 * qt) {
#pragma unroll
            for (int nt = 0; nt < 8; nt++) {
                int cb = k0 + nt * 8 + (lane & 3) * 2;
                if (cb > row0) sc[nt][0] = -1e30f;
                if (cb + 1 > row0) sc[nt][1] = -1e30f;
                if (cb > row1) sc[nt][2] = -1e30f;
                if (cb + 1 > row1) sc[nt][3] = -1e30f;
            }
        }

        float mx0 = sc[0][0], mx1 = sc[0][2];
#pragma unroll
        for (int nt = 0; nt < 8; nt++) {
            mx0 = fmaxf(mx0, fmaxf(sc[nt][0], sc[nt][1]));
            mx1 = fmaxf(mx1, fmaxf(sc[nt][2], sc[nt][3]));
        }
        mx0 = fmaxf(mx0, __shfl_xor_sync(0xffffffffu, mx0, 1));
        mx0 = fmaxf(mx0, __shfl_xor_sync(0xffffffffu, mx0, 2));
        mx1 = fmaxf(mx1, __shfl_xor_sync(0xffffffffu, mx1, 1));
        mx1 = fmaxf(mx1, __shfl_xor_sync(0xffffffffu, mx1, 2));
        const float mn0 = fmaxf(m_i[0], mx0);
        const float mn1 = fmaxf(m_i[1], mx1);
        const float alpha0 = exp2fast(m_i[0] - mn0);
        const float alpha1 = exp2fast(m_i[1] - mn1);
        m_i[0] = mn0;
        m_i[1] = mn1;

        float rs0 = 0.0f, rs1 = 0.0f;
#pragma unroll
        for (int nt = 0; nt < 8; nt++) {
            sc[nt][0] = exp2fast(sc[nt][0] - mn0);
            sc[nt][1] = exp2fast(sc[nt][1] - mn0);
            sc[nt][2] = exp2fast(sc[nt][2] - mn1);
            sc[nt][3] = exp2fast(sc[nt][3] - mn1);
            rs0 += sc[nt][0] + sc[nt][1];
            rs1 += sc[nt][2] + sc[nt][3];
        }
        rs0 += __shfl_xor_sync(0xffffffffu, rs0, 1);
        rs0 += __shfl_xor_sync(0xffffffffu, rs0, 2);
        rs1 += __shfl_xor_sync(0xffffffffu, rs1, 1);
        rs1 += __shfl_xor_sync(0xffffffffu, rs1, 2);
        l_i[0] = l_i[0] * alpha0 + rs0;
        l_i[1] = l_i[1] * alpha1 + rs1;
#pragma unroll
        for (int nt = 0; nt < 16; nt++) {
            oa[nt][0] *= alpha0;
            oa[nt][1] *= alpha0;
            oa[nt][2] *= alpha1;
            oa[nt][3] *= alpha1;
        }

#pragma unroll
        for (int kc = 0; kc < 4; kc++) {
            uint32_t ph[4], pl[4];
            split2(sc[2 * kc][0], sc[2 * kc][1], ph[0], pl[0]);
            split2(sc[2 * kc][2], sc[2 * kc][3], ph[1], pl[1]);
            split2(sc[2 * kc + 1][0], sc[2 * kc + 1][1], ph[2], pl[2]);
            split2(sc[2 * kc + 1][2], sc[2 * kc + 1][3], ph[3], pl[3]);
            const uint32_t vbase =
                (uint32_t)((kc * 16 + (lane & 15)) * ASTRIDE +
                           (((lane >> 4) << 3)) * 2);
#pragma unroll
            for (int dg = 0; dg < 8; dg++) {
                const uint32_t voff = vbase + (uint32_t)(dg * 32);
                uint32_t vh4[4], vl4[4];
                ldsm4t(vh4, Vh + voff);
                ldsm4t(vl4, Vl + voff);
                mma16816(oa[2 * dg], ph, vh4[0], vh4[1]);
                mma16816(oa[2 * dg], pl, vh4[0], vh4[1]);
                mma16816(oa[2 * dg], ph, vl4[0], vl4[1]);
                mma16816(oa[2 * dg + 1], ph, vh4[2], vh4[3]);
                mma16816(oa[2 * dg + 1], pl, vh4[2], vh4[3]);
                mma16816(oa[2 * dg + 1], ph, vl4[2], vl4[3]);
            }
        }
    }

    const float inv0 = 1.0f / l_i[0];
    const float inv1 = 1.0f / l_i[1];
    const int row0 = q0 + wr + (lane >> 2);
#pragma unroll
    for (int nt = 0; nt < 16; nt++) {
        const int d = nt * 8 + (lane & 3) * 2;
        float* p0 = &og[((size_t)(b * S_ + row0) * NH_ + h) * HD_ + d];
        float* p1 = &og[((size_t)(b * S_ + row0 + 8) * NH_ + h) * HD_ + d];
        *(float2*)p0 = make_float2(oa[nt][0] * inv0, oa[nt][1] * inv0);
        *(float2*)p1 = make_float2(oa[nt][2] * inv1, oa[nt][3] * inv1);
    }
}

// ============================================================================
// launch
// ============================================================================
extern "C" void kernel_launch(void* const* d_in, const int* in_sizes, int n_in,
                              void* d_out, int out_size) {
    const float* hidden = (const float*)d_in[0];
    const int*   pos    = (const int*)d_in[1];
    const float* Wq     = (const float*)d_in[2];
    const float* Wk     = (const float*)d_in[3];
    const float* Wv     = (const float*)d_in[4];
    const float* Wo     = (const float*)d_in[5];
    const float* qw     = (const float*)d_in[6];
    const float* kw     = (const float*)d_in[7];
    float* out = (float*)d_out;

    float *q, *k, *v, *attn, *ct, *st;
    cudaGetSymbolAddress((void**)&q,    g_q);
    cudaGetSymbolAddress((void**)&k,    g_k);
    cudaGetSymbolAddress((void**)&v,    g_v);
    cudaGetSymbolAddress((void**)&attn, g_attn);
    cudaGetSymbolAddress((void**)&ct,   g_cos);
    cudaGetSymbolAddress((void**)&st,   g_sin);

    __half *hidh, *hidl, *wqh, *wkh, *wvh, *woh, *ath, *atl;
    cudaGetSymbolAddress((void**)&hidh, g_hid_h);
    cudaGetSymbolAddress((void**)&hidl, g_hid_l);
    cudaGetSymbolAddress((void**)&wqh,  g_wq_h);
    cudaGetSymbolAddress((void**)&wkh,  g_wk_h);
    cudaGetSymbolAddress((void**)&wvh,  g_wv_h);
    cudaGetSymbolAddress((void**)&woh,  g_wo_h);
    cudaGetSymbolAddress((void**)&ath,  g_at_h);
    cudaGetSymbolAddress((void**)&atl,  g_at_l);

    // ---- pre-split inputs
    {
        int n8;
        n8 = MROWS * 1024 / 8;
        split_hl_kernel<<<(n8 + 255) / 256, 256>>>(hidden, hidh, hidl, n8);
        n8 = 1024 * 2048 / 8;
        split_h_kernel<<<(n8 + 255) / 256, 256>>>(Wq, wqh, n8);
        n8 = 1024 * 1024 / 8;
        split_h_kernel<<<(n8 + 255) / 256, 256>>>(Wk, wkh, n8);
        split_h_kernel<<<(n8 + 255) / 256, 256>>>(Wv, wvh, n8);
        n8 = 2048 * 1024 / 8;
        split_h_kernel<<<(n8 + 255) / 256, 256>>>(Wo, woh, n8);
    }

    const int gemm_smem = 3 * (int)STG_SZ;   // 87552
    cudaFuncSetAttribute(mma_gemm3_kernel,
                         cudaFuncAttributeMaxDynamicSharedMemorySize, gemm_smem);

    // QKV projections (fp16 2-term)
    mma_gemm3_kernel<<<dim3(2048 / 128, MROWS / 128), 256, gemm_smem>>>(
        hidh, hidl, wqh, q, MROWS, 2048, 1024);
    mma_gemm3_kernel<<<dim3(1024 / 128, MROWS / 128), 256, gemm_smem>>>(
        hidh, hidl, wkh, k, MROWS, 1024, 1024);
    mma_gemm3_kernel<<<dim3(1024 / 128, MROWS / 128), 256, gemm_smem>>>(
        hidh, hidl, wvh, v, MROWS, 1024, 1024);

    // RoPE table + RMSNorm/RoPE
    rope_table_kernel<<<(S_ * 64 + 255) / 256, 256>>>(pos, ct, st);
    {
        int total_warps = B_ * S_ * (NH_ + NKV_);
        norm_rope_kernel<<<total_warps / 8, 256>>>(q, k, qw, kw, ct, st);
    }

    // attention (bf16 3-term — unchanged)
    {
        const int attn_smem = 139264;
        cudaFuncSetAttribute(attn_mma_kernel,
                             cudaFuncAttributeMaxDynamicSharedMemorySize,
                             attn_smem);
        attn_mma_kernel<<<dim3(S_ / 128, B_ * NH_), 256, attn_smem>>>(
            q, k, v, attn);
    }

    // split attention output, then output projection (fp16 2-term)
    {
        int n8 = MROWS * 2048 / 8;
        split_hl_kernel<<<(n8 + 255) / 256, 256>>>(attn, ath, atl, n8);
    }
    mma_gemm3_kernel<<<dim3(1024 / 128, MROWS / 128), 256, gemm_smem>>>(
        ath, atl, woh, out, MROWS, 1024, 2048);
}

// round 8
// speedup vs baseline: 3.2476x; 1.1221x over previous
#include <cuda_runtime.h>
#include <cuda_bf16.h>
#include <cuda_fp16.h>
#include <math.h>
#include <stdint.h>

#define B_   2
#define S_   2048
#define NH_  16
#define NKV_ 8
#define HD_  128
#define MROWS (B_ * S_)          // 4096

// ---------------- scratch (device globals; no allocation allowed) ----------
__device__ float g_q[(size_t)B_ * S_ * NH_ * HD_];
__device__ float g_k[(size_t)B_ * S_ * NKV_ * HD_];
__device__ float g_v[(size_t)B_ * S_ * NKV_ * HD_];
__device__ float g_cos[S_ * 64];
__device__ float g_sin[S_ * 64];
// pre-split fp16 copies (A-side: hi+lo; B-side: hi only)
__device__ __half g_hid_h[(size_t)MROWS * 1024];
__device__ __half g_hid_l[(size_t)MROWS * 1024];
__device__ __half g_wq_h[(size_t)1024 * 2048];
__device__ __half g_wk_h[(size_t)1024 * 1024];
__device__ __half g_wv_h[(size_t)1024 * 1024];
__device__ __half g_wo_h[(size_t)2048 * 1024];
__device__ __half g_at_h[(size_t)MROWS * 2048];
__device__ __half g_at_l[(size_t)MROWS * 2048];

// ---------------- helpers ---------------------------------------------------
__device__ __forceinline__ uint32_t smem_u32(const void* p) {
    uint32_t a;
    asm("{ .reg .u64 t; cvta.to.shared.u64 t, %1; cvt.u32.u64 %0, t; }"
        : "=r"(a) : "l"(p));
    return a;
}
__device__ __forceinline__ void ldsm4(uint32_t* r, uint32_t addr) {
    asm volatile("ldmatrix.sync.aligned.m8n8.x4.shared.b16 {%0,%1,%2,%3}, [%4];"
                 : "=r"(r[0]), "=r"(r[1]), "=r"(r[2]), "=r"(r[3]) : "r"(addr));
}
__device__ __forceinline__ void ldsm4t(uint32_t* r, uint32_t addr) {
    asm volatile("ldmatrix.sync.aligned.m8n8.x4.trans.shared.b16 {%0,%1,%2,%3}, [%4];"
                 : "=r"(r[0]), "=r"(r[1]), "=r"(r[2]), "=r"(r[3]) : "r"(addr));
}
// fp16 mma, f32 accum
__device__ __forceinline__ void mma16816h(float* c, const uint32_t* a,
                                          uint32_t b0, uint32_t b1) {
    asm volatile(
        "mma.sync.aligned.m16n8k16.row.col.f32.f16.f16.f32 "
        "{%0,%1,%2,%3}, {%4,%5,%6,%7}, {%8,%9}, {%0,%1,%2,%3};"
        : "+f"(c[0]), "+f"(c[1]), "+f"(c[2]), "+f"(c[3])
        : "r"(a[0]), "r"(a[1]), "r"(a[2]), "r"(a[3]), "r"(b0), "r"(b1));
}
__device__ __forceinline__ void sts128(uint32_t addr, uint32_t a, uint32_t b,
                                       uint32_t c, uint32_t d) {
    asm volatile("st.shared.v4.b32 [%0], {%1, %2, %3, %4};"
                 :: "r"(addr), "r"(a), "r"(b), "r"(c), "r"(d));
}
// fp16 hi/lo split (packed half2)
__device__ __forceinline__ void split2h(float a, float b, uint32_t& hi, uint32_t& lo) {
    __half2 h = __floats2half2_rn(a, b);
    float2 hf = __half22float2(h);
    __half2 l = __floats2half2_rn(a - hf.x, b - hf.y);
    hi = *(uint32_t*)&h;
    lo = *(uint32_t*)&l;
}
__device__ __forceinline__ uint32_t cvt2h(float a, float b) {
    __half2 h = __floats2half2_rn(a, b);
    return *(uint32_t*)&h;
}
// fast 2^y on the FMA pipe (no MUFU)
__device__ __forceinline__ float exp2fast(float y) {
    y = fmaxf(y, -126.0f);
    float r = y + 12582912.0f;
    float kf = r - 12582912.0f;
    float f = y - kf;
    float p = 1.3333558146e-3f;
    p = fmaf(p, f, 9.6181291076e-3f);
    p = fmaf(p, f, 5.5504108664e-2f);
    p = fmaf(p, f, 2.4022650696e-1f);
    p = fmaf(p, f, 6.9314718056e-1f);
    p = fmaf(p, f, 1.0f);
    return __int_as_float(__float_as_int(p) + (__float_as_int(r) << 23));
}

#define CP_ASYNC16(dst, src) \
    asm volatile("cp.async.cg.shared.global [%0], [%1], 16;" \
                 :: "r"(dst), "l"(src))
#define CP_COMMIT() asm volatile("cp.async.commit_group;" ::: "memory")
#define CP_WAIT1()  asm volatile("cp.async.wait_group 1;" ::: "memory")

// ============================================================================
// split kernels: fp32 -> fp16 hi (+ lo)
// ============================================================================
__global__ void split_hl_kernel(const float* __restrict__ in,
                                __half* __restrict__ hi,
                                __half* __restrict__ lo, int n8) {
    int idx = blockIdx.x * blockDim.x + threadIdx.x;
    if (idx >= n8) return;
    const float4 x0 = ((const float4*)in)[2 * idx];
    const float4 x1 = ((const float4*)in)[2 * idx + 1];
    uint4 h, l;
    split2h(x0.x, x0.y, h.x, l.x);
    split2h(x0.z, x0.w, h.y, l.y);
    split2h(x1.x, x1.y, h.z, l.z);
    split2h(x1.z, x1.w, h.w, l.w);
    ((uint4*)hi)[idx] = h;
    ((uint4*)lo)[idx] = l;
}

__global__ void split_h_kernel(const float* __restrict__ in,
                               __half* __restrict__ hi, int n8) {
    int idx = blockIdx.x * blockDim.x + threadIdx.x;
    if (idx >= n8) return;
    const float4 x0 = ((const float4*)in)[2 * idx];
    const float4 x1 = ((const float4*)in)[2 * idx + 1];
    uint4 h;
    h.x = cvt2h(x0.x, x0.y);
    h.y = cvt2h(x0.z, x0.w);
    h.z = cvt2h(x1.x, x1.y);
    h.w = cvt2h(x1.z, x1.w);
    ((uint4*)hi)[idx] = h;
}

// ============================================================================
// GEMM v3 (unchanged R7 — proven): fp16 2-term Ah*Bh + Al*Bh.
// ============================================================================
#define STG_SZ 29184u

__global__ __launch_bounds__(256, 2)
void mma_gemm3_kernel(const __half* __restrict__ Ah,
                      const __half* __restrict__ Al,
                      const __half* __restrict__ Bh,
                      float* __restrict__ C, int M, int N, int K) {
    extern __shared__ __align__(16) char dsm[];
    const uint32_t sbase = smem_u32(dsm);

    const int tid  = threadIdx.x;
    const int lane = tid & 31;
    const int wid  = tid >> 5;
    const int m0 = blockIdx.y * 128;
    const int n0 = blockIdx.x * 128;
    const int wm = (wid >> 2) * 64;
    const int wn = (wid & 3) * 32;

    float acc[4][4][4];
#pragma unroll
    for (int i = 0; i < 4; i++)
#pragma unroll
        for (int j = 0; j < 4; j++)
#pragma unroll
            for (int r = 0; r < 4; r++) acc[i][j][r] = 0.0f;

    const int a_row = tid >> 1;
    const int a_off = (tid & 1) * 16;
    const int b_kr  = tid >> 3;
    const int b_off = (tid & 7) * 16;

    const int nch = K >> 5;

#pragma unroll
    for (int c = 0; c < 2; c++) {
        const uint32_t st = sbase + (uint32_t)c * STG_SZ;
        const __half* ah = Ah + (size_t)(m0 + a_row) * K + c * 32 + a_off;
        const __half* al = Al + (size_t)(m0 + a_row) * K + c * 32 + a_off;
        uint32_t da = st + (uint32_t)(a_row * 80 + a_off * 2);
        CP_ASYNC16(da, ah);
        CP_ASYNC16(da + 16, ah + 8);
        CP_ASYNC16(da + 10240, al);
        CP_ASYNC16(da + 10256, al + 8);
        const __half* bh = Bh + (size_t)(c * 32 + b_kr) * N + n0 + b_off;
        uint32_t db = st + 20480u + (uint32_t)(b_kr * 272 + b_off * 2);
        CP_ASYNC16(db, bh);
        CP_ASYNC16(db + 16, bh + 8);
        CP_COMMIT();
    }

    for (int c = 0; c < nch; c++) {
        CP_WAIT1();
        __syncthreads();

        const uint32_t st = sbase + (uint32_t)(c % 3) * STG_SZ;
#pragma unroll
        for (int ks = 0; ks < 2; ks++) {
            uint32_t ah[4][4], al[4][4], bh[2][4];
            const uint32_t aoff =
                st + (uint32_t)((wm + (lane & 15)) * 80 +
                                (ks * 16 + ((lane >> 4) << 3)) * 2);
#pragma unroll
            for (int mt = 0; mt < 4; mt++) {
                ldsm4(ah[mt], aoff + mt * 16 * 80);
                ldsm4(al[mt], aoff + mt * 16 * 80 + 10240);
            }
            const uint32_t bbase =
                st + 20480u + (uint32_t)((ks * 16 + (lane & 15)) * 272 +
                                         (wn + ((lane >> 4) << 3)) * 2);
#pragma unroll
            for (int ng = 0; ng < 2; ng++)
                ldsm4t(bh[ng], bbase + ng * 32);
#pragma unroll
            for (int mt = 0; mt < 4; mt++)
#pragma unroll
                for (int nt = 0; nt < 4; nt++) {
                    const int ng = nt >> 1;
                    const int hf = (nt & 1) * 2;
                    mma16816h(acc[mt][nt], ah[mt], bh[ng][hf], bh[ng][hf + 1]);
                    mma16816h(acc[mt][nt], al[mt], bh[ng][hf], bh[ng][hf + 1]);
                }
        }
        __syncthreads();

        const int nc = c + 2;
        if (nc < nch) {
            const uint32_t st2 = sbase + (uint32_t)(nc % 3) * STG_SZ;
            const __half* ahp = Ah + (size_t)(m0 + a_row) * K + nc * 32 + a_off;
            const __half* alp = Al + (size_t)(m0 + a_row) * K + nc * 32 + a_off;
            uint32_t da = st2 + (uint32_t)(a_row * 80 + a_off * 2);
            CP_ASYNC16(da, ahp);
            CP_ASYNC16(da + 16, ahp + 8);
            CP_ASYNC16(da + 10240, alp);
            CP_ASYNC16(da + 10256, alp + 8);
            const __half* bhp = Bh + (size_t)(nc * 32 + b_kr) * N + n0 + b_off;
            uint32_t db = st2 + 20480u + (uint32_t)(b_kr * 272 + b_off * 2);
            CP_ASYNC16(db, bhp);
            CP_ASYNC16(db + 16, bhp + 8);
        }
        CP_COMMIT();
    }

#pragma unroll
    for (int mt = 0; mt < 4; mt++)
#pragma unroll
        for (int nt = 0; nt < 4; nt++) {
            int row = m0 + wm + mt * 16 + (lane >> 2);
            int col = n0 + wn + nt * 8 + (lane & 3) * 2;
            *(float2*)&C[(size_t)row * N + col] =
                make_float2(acc[mt][nt][0], acc[mt][nt][1]);
            *(float2*)&C[(size_t)(row + 8) * N + col] =
                make_float2(acc[mt][nt][2], acc[mt][nt][3]);
        }
}

// ============================================================================
// RoPE cos/sin table
// ============================================================================
__global__ void rope_table_kernel(const int* __restrict__ pos,
                                  float* __restrict__ ctab,
                                  float* __restrict__ stab) {
    int idx = blockIdx.x * blockDim.x + threadIdx.x;
    if (idx >= S_ * 64) return;
    int s  = idx >> 6;
    int fi = idx & 63;
    float inv = (float)exp(-13.815510557964274 * (double)fi / 64.0);
    float ang = (float)pos[s] * inv;
    float c, sn;
    sincosf(ang, &sn, &c);
    ctab[idx] = c;
    stab[idx] = sn;
}

// ============================================================================
// RMSNorm + RoPE in-place over g_q and g_k.
// ============================================================================
__global__ void norm_rope_kernel(float* __restrict__ q, float* __restrict__ k,
                                 const float* __restrict__ qw,
                                 const float* __restrict__ kw,
                                 const float* __restrict__ ctab,
                                 const float* __restrict__ stab) {
    const int warp = (blockIdx.x * blockDim.x + threadIdx.x) >> 5;
    const int lane = threadIdx.x & 31;
    const int QROWS = B_ * S_ * NH_;

    float* ptr;
    const float* w;
    int s;
    if (warp < QROWS) {
        ptr = q + (size_t)warp * HD_;
        w = qw;
        s = (warp / NH_) % S_;
    } else {
        int r = warp - QROWS;
        ptr = k + (size_t)r * HD_;
        w = kw;
        s = (r / NKV_) % S_;
    }

    float4 x = ((const float4*)ptr)[lane];
    float ss = x.x * x.x + x.y * x.y + x.z * x.z + x.w * x.w;
#pragma unroll
    for (int off = 16; off; off >>= 1)
        ss += __shfl_xor_sync(0xffffffffu, ss, off);
    float rms = rsqrtf(ss * (1.0f / 128.0f) + 1e-6f);

    const int d0 = lane * 4;
    float xn[4];
    xn[0] = x.x * rms * w[d0 + 0];
    xn[1] = x.y * rms * w[d0 + 1];
    xn[2] = x.z * rms * w[d0 + 2];
    xn[3] = x.w * rms * w[d0 + 3];

    float out[4];
#pragma unroll
    for (int j = 0; j < 4; j++) {
        int fi = (d0 + j) & 63;
        float c  = ctab[s * 64 + fi];
        float sn = stab[s * 64 + fi];
        float partner = __shfl_xor_sync(0xffffffffu, xn[j], 16);
        out[j] = (lane < 16) ? (xn[j] * c - partner * sn)
                             : (xn[j] * c + partner * sn);
    }
    ((float4*)ptr)[lane] = make_float4(out[0], out[1], out[2], out[3]);
}

// ============================================================================
// Flash attention, fp16 2-term: S = (Qh+Ql)*Kh, O = (Ph+Pl)*Vh.
// BM=128 (CTA), BN=64/iter, 8 warps, causal, GQA. Epilogue writes fp16 hi/lo
// directly to the Wo-GEMM input buffers (no fp32 round trip).
// SMEM: Qh@0 Ql@34816 | Kh@69632 | Vh@87040  => 104448 B.
// ============================================================================
#define ASTRIDE 272

__global__ __launch_bounds__(256, 1)
void attn_mma_kernel(const float* __restrict__ qg, const float* __restrict__ kg,
                     const float* __restrict__ vg,
                     __half* __restrict__ oh, __half* __restrict__ ol) {
    extern __shared__ __align__(16) char asmem[];
    const uint32_t sb = smem_u32(asmem);
    const uint32_t Qh = sb, Ql = sb + 34816u;
    const uint32_t Kh = sb + 69632u;
    const uint32_t Vh = sb + 87040u;

    const int tid = threadIdx.x;
    const int lane = tid & 31;
    const int wid = tid >> 5;
    const int bh = blockIdx.y;
    const int b  = bh >> 4;
    const int h  = bh & 15;
    const int hk = h >> 1;
    const int qt = gridDim.x - 1 - blockIdx.x;
    const int q0 = qt * 128;
    const int wr = wid * 16;
    const float qscale = 0.1275174985f;   // 1/sqrt(128) * log2(e)

    // ---- load Q tile (pre-scaled, fp16 hi/lo)
    {
        const int r = tid >> 1;
        const int hf = (tid & 1) * 64;
        const float* qp = &qg[((size_t)(b * S_ + q0 + r) * NH_ + h) * HD_ + hf];
        const uint32_t off = (uint32_t)(r * ASTRIDE + hf * 2);
#pragma unroll
        for (int j = 0; j < 8; j++) {
            float4 x0 = ((const float4*)qp)[2 * j];
            float4 x1 = ((const float4*)qp)[2 * j + 1];
            uint32_t h0, h1, h2, h3, l0, l1, l2, l3;
            split2h(x0.x * qscale, x0.y * qscale, h0, l0);
            split2h(x0.z * qscale, x0.w * qscale, h1, l1);
            split2h(x1.x * qscale, x1.y * qscale, h2, l2);
            split2h(x1.z * qscale, x1.w * qscale, h3, l3);
            sts128(Qh + off + j * 16, h0, h1, h2, h3);
            sts128(Ql + off + j * 16, l0, l1, l2, l3);
        }
    }

    float oa[16][4];
    float m_i[2], l_i[2];
#pragma unroll
    for (int nt = 0; nt < 16; nt++)
#pragma unroll
        for (int r = 0; r < 4; r++) oa[nt][r] = 0.0f;
    m_i[0] = m_i[1] = -1e30f;
    l_i[0] = l_i[1] = 0.0f;

    const int nkt = 2 * (qt + 1);
    for (int kt = 0; kt < nkt; kt++) {
        const int k0 = kt * 64;
        __syncthreads();
        // ---- load K,V tiles (fp16 hi only)
        {
            const int r = tid >> 2;
            const int qd = (tid & 3) * 32;
            const size_t gro = ((size_t)(b * S_ + k0 + r) * NKV_ + hk) * HD_ + qd;
            const uint32_t off = (uint32_t)(r * ASTRIDE + qd * 2);
            const float* kp = &kg[gro];
            const float* vp = &vg[gro];
#pragma unroll
            for (int j = 0; j < 4; j++) {
                float4 x0 = ((const float4*)kp)[2 * j];
                float4 x1 = ((const float4*)kp)[2 * j + 1];
                sts128(Kh + off + j * 16,
                       cvt2h(x0.x, x0.y), cvt2h(x0.z, x0.w),
                       cvt2h(x1.x, x1.y), cvt2h(x1.z, x1.w));
            }
#pragma unroll
            for (int j = 0; j < 4; j++) {
                float4 x0 = ((const float4*)vp)[2 * j];
                float4 x1 = ((const float4*)vp)[2 * j + 1];
                sts128(Vh + off + j * 16,
                       cvt2h(x0.x, x0.y), cvt2h(x0.z, x0.w),
                       cvt2h(x1.x, x1.y), cvt2h(x1.z, x1.w));
            }
        }
        __syncthreads();

        // ---- S = (Qh+Ql) @ Kh^T
        float sc[8][4];
#pragma unroll
        for (int nt = 0; nt < 8; nt++)
#pragma unroll
            for (int r = 0; r < 4; r++) sc[nt][r] = 0.0f;

#pragma unroll
        for (int kc = 0; kc < 8; kc++) {
            const uint32_t aoff =
                (uint32_t)((wr + (lane & 15)) * ASTRIDE +
                           (kc * 16 + ((lane >> 4) << 3)) * 2);
            uint32_t qh4[4], ql4[4];
            ldsm4(qh4, Qh + aoff);
            ldsm4(ql4, Ql + aoff);
            const uint32_t bbase =
                (uint32_t)((((lane >> 4) << 3) + (lane & 7)) * ASTRIDE +
                           (kc * 16 + ((lane >> 3) & 1) * 8) * 2);
#pragma unroll
            for (int bg = 0; bg < 4; bg++) {
                const uint32_t boff = bbase + (uint32_t)(bg * 16 * ASTRIDE);
                uint32_t kh4[4];
                ldsm4(kh4, Kh + boff);
                mma16816h(sc[2 * bg], qh4, kh4[0], kh4[1]);
                mma16816h(sc[2 * bg], ql4, kh4[0], kh4[1]);
                mma16816h(sc[2 * bg + 1], qh4, kh4[2], kh4[3]);
                mma16816h(sc[2 * bg + 1], ql4, kh4[2], kh4[3]);
            }
        }

        // ---- causal mask (diagonal tiles only)
        const int row0 = q0 + wr + (lane >> 2);
        const int row1 = row0 + 8;
        if (kt >= 2 * qt) {
#pragma unroll
            for (int nt = 0; nt < 8; nt++) {
                int cb = k0 + nt * 8 + (lane & 3) * 2;
                if (cb > row0) sc[nt][0] = -1e30f;
                if (cb + 1 > row0) sc[nt][1] = -1e30f;
                if (cb > row1) sc[nt][2] = -1e30f;
                if (cb + 1 > row1) sc[nt][3] = -1e30f;
            }
        }

        // ---- online softmax (base-2, poly exp2)
        float mx0 = sc[0][0], mx1 = sc[0][2];
#pragma unroll
        for (int nt = 0; nt < 8; nt++) {
            mx0 = fmaxf(mx0, fmaxf(sc[nt][0], sc[nt][1]));
            mx1 = fmaxf(mx1, fmaxf(sc[nt][2], sc[nt][3]));
        }
        mx0 = fmaxf(mx0, __shfl_xor_sync(0xffffffffu, mx0, 1));
        mx0 = fmaxf(mx0, __shfl_xor_sync(0xffffffffu, mx0, 2));
        mx1 = fmaxf(mx1, __shfl_xor_sync(0xffffffffu, mx1, 1));
        mx1 = fmaxf(mx1, __shfl_xor_sync(0xffffffffu, mx1, 2));
        const float mn0 = fmaxf(m_i[0], mx0);
        const float mn1 = fmaxf(m_i[1], mx1);
        const float alpha0 = exp2fast(m_i[0] - mn0);
        const float alpha1 = exp2fast(m_i[1] - mn1);
        m_i[0] = mn0;
        m_i[1] = mn1;

        float rs0 = 0.0f, rs1 = 0.0f;
#pragma unroll
        for (int nt = 0; nt < 8; nt++) {
            sc[nt][0] = exp2fast(sc[nt][0] - mn0);
            sc[nt][1] = exp2fast(sc[nt][1] - mn0);
            sc[nt][2] = exp2fast(sc[nt][2] - mn1);
            sc[nt][3] = exp2fast(sc[nt][3] - mn1);
            rs0 += sc[nt][0] + sc[nt][1];
            rs1 += sc[nt][2] + sc[nt][3];
        }
        rs0 += __shfl_xor_sync(0xffffffffu, rs0, 1);
        rs0 += __shfl_xor_sync(0xffffffffu, rs0, 2);
        rs1 += __shfl_xor_sync(0xffffffffu, rs1, 1);
        rs1 += __shfl_xor_sync(0xffffffffu, rs1, 2);
        l_i[0] = l_i[0] * alpha0 + rs0;
        l_i[1] = l_i[1] * alpha1 + rs1;
#pragma unroll
        for (int nt = 0; nt < 16; nt++) {
            oa[nt][0] *= alpha0;
            oa[nt][1] *= alpha0;
            oa[nt][2] *= alpha1;
            oa[nt][3] *= alpha1;
        }

        // ---- O += (Ph+Pl) @ Vh
#pragma unroll
        for (int kc = 0; kc < 4; kc++) {
            uint32_t ph[4], pl[4];
            split2h(sc[2 * kc][0], sc[2 * kc][1], ph[0], pl[0]);
            split2h(sc[2 * kc][2], sc[2 * kc][3], ph[1], pl[1]);
            split2h(sc[2 * kc + 1][0], sc[2 * kc + 1][1], ph[2], pl[2]);
            split2h(sc[2 * kc + 1][2], sc[2 * kc + 1][3], ph[3], pl[3]);
            const uint32_t vbase =
                (uint32_t)((kc * 16 + (lane & 15)) * ASTRIDE +
                           (((lane >> 4) << 3)) * 2);
#pragma unroll
            for (int dg = 0; dg < 8; dg++) {
                const uint32_t voff = vbase + (uint32_t)(dg * 32);
                uint32_t vh4[4];
                ldsm4t(vh4, Vh + voff);
                mma16816h(oa[2 * dg], ph, vh4[0], vh4[1]);
                mma16816h(oa[2 * dg], pl, vh4[0], vh4[1]);
                mma16816h(oa[2 * dg + 1], ph, vh4[2], vh4[3]);
                mma16816h(oa[2 * dg + 1], pl, vh4[2], vh4[3]);
            }
        }
    }

    // ---- epilogue: O /= l, write fp16 hi/lo directly (Wo-GEMM input layout)
    const float inv0 = 1.0f / l_i[0];
    const float inv1 = 1.0f / l_i[1];
    const int row0 = q0 + wr + (lane >> 2);
#pragma unroll
    for (int nt = 0; nt < 16; nt++) {
        const int d = nt * 8 + (lane & 3) * 2;
        const size_t i0 = (size_t)(b * S_ + row0) * 2048 + h * 128 + d;
        const size_t i1 = (size_t)(b * S_ + row0 + 8) * 2048 + h * 128 + d;
        uint32_t hh, hl;
        split2h(oa[nt][0] * inv0, oa[nt][1] * inv0, hh, hl);
        *(uint32_t*)&oh[i0] = hh;
        *(uint32_t*)&ol[i0] = hl;
        split2h(oa[nt][2] * inv1, oa[nt][3] * inv1, hh, hl);
        *(uint32_t*)&oh[i1] = hh;
        *(uint32_t*)&ol[i1] = hl;
    }
}

// ============================================================================
// launch
// ============================================================================
extern "C" void kernel_launch(void* const* d_in, const int* in_sizes, int n_in,
                              void* d_out, int out_size) {
    const float* hidden = (const float*)d_in[0];
    const int*   pos    = (const int*)d_in[1];
    const float* Wq     = (const float*)d_in[2];
    const float* Wk     = (const float*)d_in[3];
    const float* Wv     = (const float*)d_in[4];
    const float* Wo     = (const float*)d_in[5];
    const float* qw     = (const float*)d_in[6];
    const float* kw     = (const float*)d_in[7];
    float* out = (float*)d_out;

    float *q, *k, *v, *ct, *st;
    cudaGetSymbolAddress((void**)&q,  g_q);
    cudaGetSymbolAddress((void**)&k,  g_k);
    cudaGetSymbolAddress((void**)&v,  g_v);
    cudaGetSymbolAddress((void**)&ct, g_cos);
    cudaGetSymbolAddress((void**)&st, g_sin);

    __half *hidh, *hidl, *wqh, *wkh, *wvh, *woh, *ath, *atl;
    cudaGetSymbolAddress((void**)&hidh, g_hid_h);
    cudaGetSymbolAddress((void**)&hidl, g_hid_l);
    cudaGetSymbolAddress((void**)&wqh,  g_wq_h);
    cudaGetSymbolAddress((void**)&wkh,  g_wk_h);
    cudaGetSymbolAddress((void**)&wvh,  g_wv_h);
    cudaGetSymbolAddress((void**)&woh,  g_wo_h);
    cudaGetSymbolAddress((void**)&ath,  g_at_h);
    cudaGetSymbolAddress((void**)&atl,  g_at_l);

    // ---- pre-split inputs
    {
        int n8;
        n8 = MROWS * 1024 / 8;
        split_hl_kernel<<<(n8 + 255) / 256, 256>>>(hidden, hidh, hidl, n8);
        n8 = 1024 * 2048 / 8;
        split_h_kernel<<<(n8 + 255) / 256, 256>>>(Wq, wqh, n8);
        n8 = 1024 * 1024 / 8;
        split_h_kernel<<<(n8 + 255) / 256, 256>>>(Wk, wkh, n8);
        split_h_kernel<<<(n8 + 255) / 256, 256>>>(Wv, wvh, n8);
        n8 = 2048 * 1024 / 8;
        split_h_kernel<<<(n8 + 255) / 256, 256>>>(Wo, woh, n8);
    }

    const int gemm_smem = 3 * (int)STG_SZ;   // 87552
    cudaFuncSetAttribute(mma_gemm3_kernel,
                         cudaFuncAttributeMaxDynamicSharedMemorySize, gemm_smem);

    // QKV projections (fp16 2-term)
    mma_gemm3_kernel<<<dim3(2048 / 128, MROWS / 128), 256, gemm_smem>>>(
        hidh, hidl, wqh, q, MROWS, 2048, 1024);
    mma_gemm3_kernel<<<dim3(1024 / 128, MROWS / 128), 256, gemm_smem>>>(
        hidh, hidl, wkh, k, MROWS, 1024, 1024);
    mma_gemm3_kernel<<<dim3(1024 / 128, MROWS / 128), 256, gemm_smem>>>(
        hidh, hidl, wvh, v, MROWS, 1024, 1024);

    // RoPE table + RMSNorm/RoPE
    rope_table_kernel<<<(S_ * 64 + 255) / 256, 256>>>(pos, ct, st);
    {
        int total_warps = B_ * S_ * (NH_ + NKV_);
        norm_rope_kernel<<<total_warps / 8, 256>>>(q, k, qw, kw, ct, st);
    }

    // attention (fp16 2-term; writes fp16 hi/lo directly)
    {
        const int attn_smem = 104448;
        cudaFuncSetAttribute(attn_mma_kernel,
                             cudaFuncAttributeMaxDynamicSharedMemorySize,
                             attn_smem);
        attn_mma_kernel<<<dim3(S_ / 128, B_ * NH_), 256, attn_smem>>>(
            q, k, v, ath, atl);
    }

    // output projection (fp16 2-term)
    mma_gemm3_kernel<<<dim3(1024 / 128, MROWS / 128), 256, gemm_smem>>>(
        ath, atl, woh, out, MROWS, 1024, 2048);
}